// round 5
// baseline (speedup 1.0000x reference)
#include <cuda_runtime.h>
#include <math.h>
#include <stdint.h>

#define BATCH   1024
#define SDIM    2048
#define N_ITER  16
#define PITERS  24
#define KCHUNK  32
#define NCHUNK  (SDIM / KCHUNK)    // 64
#define NTHREADS 256

// ---------------- static device scratch ----------------
__device__ __align__(256) float g_yth[BATCH * SDIM];
__device__ __align__(256) float g_ydl[BATCH * SDIM];
__device__ __align__(256) float g_xth[BATCH * SDIM];
__device__ __align__(256) float g_xdl[BATCH * SDIM];
__device__ __align__(256) float g_u  [BATCH * SDIM];
__device__ __align__(256) float g_res[BATCH * SDIM];
__device__ __align__(256) float g_WT [SDIM * SDIM];
__device__ __align__(256) float g_MA [SDIM * SDIM];
__device__ __align__(256) float g_MB [SDIM * SDIM];
__device__ __align__(256) float g_vec [SDIM];
__device__ __align__(256) float g_wvec[SDIM];
__device__ float g_scal[4];   // [0] = 1/L, [1] = thresh

// SMEM per stage: Ahi[0,8K) Alo[8K,16K) Bhi[16K,20K) Blo[20K,24K)
#define STAGE_B    24576
#define SMEM_TOTAL (2 * STAGE_B)   // 48 KB -> 2 CTAs/SM

static __device__ __forceinline__ uint32_t smem_u32(const void* p) {
    uint32_t a;
    asm("{ .reg .u64 t; cvta.to.shared.u64 t, %1; cvt.u32.u64 %0, t; }" : "=r"(a) : "l"(p));
    return a;
}
static __device__ __forceinline__ void lds128(uint32_t* r, uint32_t a) {
    asm volatile("ld.shared.v4.b32 {%0,%1,%2,%3}, [%4];"
                 : "=r"(r[0]), "=r"(r[1]), "=r"(r[2]), "=r"(r[3]) : "r"(a));
}
static __device__ __forceinline__ void lds64(uint32_t* r, uint32_t a) {
    asm volatile("ld.shared.v2.b32 {%0,%1}, [%2];" : "=r"(r[0]), "=r"(r[1]) : "r"(a));
}
static __device__ __forceinline__ void sts32(uint32_t a, uint32_t v) {
    asm volatile("st.shared.b32 [%0], %1;" :: "r"(a), "r"(v));
}
static __device__ __forceinline__ void mma16816(float* d, const uint32_t* a, const uint32_t* b) {
    asm volatile(
        "mma.sync.aligned.m16n8k16.row.col.f32.bf16.bf16.f32 "
        "{%0,%1,%2,%3}, {%4,%5,%6,%7}, {%8,%9}, {%0,%1,%2,%3};"
        : "+f"(d[0]), "+f"(d[1]), "+f"(d[2]), "+f"(d[3])
        : "r"(a[0]), "r"(a[1]), "r"(a[2]), "r"(a[3]), "r"(b[0]), "r"(b[1]));
}

// split 8 fp32 into 4 packed bf16x2 hi (truncated) + 4 lo (residual)
static __device__ __forceinline__ void split8(float4 a, float4 b, uint32_t* h, uint32_t* l) {
    uint32_t ux = __float_as_uint(a.x), uy = __float_as_uint(a.y);
    uint32_t uz = __float_as_uint(a.z), uw = __float_as_uint(a.w);
    uint32_t vx = __float_as_uint(b.x), vy = __float_as_uint(b.y);
    uint32_t vz = __float_as_uint(b.z), vw = __float_as_uint(b.w);
    h[0] = __byte_perm(ux, uy, 0x7632);
    h[1] = __byte_perm(uz, uw, 0x7632);
    h[2] = __byte_perm(vx, vy, 0x7632);
    h[3] = __byte_perm(vz, vw, 0x7632);
    float r0 = a.x - __uint_as_float(ux & 0xFFFF0000u);
    float r1 = a.y - __uint_as_float(uy & 0xFFFF0000u);
    float r2 = a.z - __uint_as_float(uz & 0xFFFF0000u);
    float r3 = a.w - __uint_as_float(uw & 0xFFFF0000u);
    float r4 = b.x - __uint_as_float(vx & 0xFFFF0000u);
    float r5 = b.y - __uint_as_float(vy & 0xFFFF0000u);
    float r6 = b.z - __uint_as_float(vz & 0xFFFF0000u);
    float r7 = b.w - __uint_as_float(vw & 0xFFFF0000u);
    asm("cvt.rn.bf16x2.f32 %0, %1, %2;" : "=r"(l[0]) : "f"(r1), "f"(r0));
    asm("cvt.rn.bf16x2.f32 %0, %1, %2;" : "=r"(l[1]) : "f"(r3), "f"(r2));
    asm("cvt.rn.bf16x2.f32 %0, %1, %2;" : "=r"(l[2]) : "f"(r5), "f"(r4));
    asm("cvt.rn.bf16x2.f32 %0, %1, %2;" : "=r"(l[3]) : "f"(r7), "f"(r6));
}

static __device__ __forceinline__ float softthr(float v, float th) {
    float a = fabsf(v) - th;
    return a > 0.0f ? copysignf(a, v) : 0.0f;
}

// ---------------------------------------------------------------------------
// C[m,n] = sum_k A[m,k] * B[n,k], K=2048. CTA tile 128(M)x64(N), 8 warps (4x2),
// warp tile 32x32. SYM=1: triangular 1D grid + mirrored write (symmetric C).
// EPI 0: C=acc*scale   EPI 1: res/u   EPI 2: FISTA update (+out)
// ---------------------------------------------------------------------------
template<int EPI, int SYM>
__global__ void __launch_bounds__(NTHREADS, 2)
mma_gemm(const float* __restrict__ A, const float* __restrict__ Bm,
         float* __restrict__ C, float scale,
         const float* __restrict__ src, const float* __restrict__ Yg,
         float* __restrict__ resv, float* __restrict__ uv,
         float* __restrict__ xth, float* __restrict__ yth,
         float* __restrict__ xdl, float* __restrict__ ydl,
         float* __restrict__ outp, float mom)
{
    extern __shared__ char smem[];
    const uint32_t sb = smem_u32(smem);
    const int tid = threadIdx.x;
    const int wid = tid >> 5, lid = tid & 31;
    const int wm = wid & 3, wn = wid >> 2;   // 4 x 2 warps over (M, N)

    int row0, col0, bxi = 0, byi = 0;
    if (SYM) {
        int t = blockIdx.x;
        int by = (int)((sqrtf(4.0f * t + 1.0f) - 1.0f) * 0.5f);
        while ((by + 1) * (by + 2) <= t) by++;
        while (by * (by + 1) > t) by--;
        int bx = t - by * (by + 1);      // 0 .. 2*by+1
        row0 = by * 128; col0 = bx * 64;
        bxi = bx; byi = by;
    } else {
        row0 = blockIdx.y * 128; col0 = blockIdx.x * 64;
    }

    // ---- producer mapping ----
    const int rA  = tid & 127;
    const int c8a = (tid >> 7) * 2;          // 0 or 2 (two adjacent k8 groups)
    const int rB  = tid & 63;
    const int c8b = tid >> 6;                // 0..3

    // A STS bases for items j=0,1 (c8 = c8a + j)
    uint32_t aSt[2];
#pragma unroll
    for (int j = 0; j < 2; j++) {
        int c8 = c8a + j;
        aSt[j] = sb + (uint32_t)(((((rA >> 4) * 2 + (c8 >> 1)) << 9)
                 + ((rA & 7) << 6) + (((c8 & 1) * 2 + ((rA >> 3) & 1)) << 2)));
    }
    const uint32_t bSt = sb + 16384u + (uint32_t)((((rB >> 3) * 2 + (c8b >> 1)) << 8)
                 + ((rB & 7) << 5) + ((c8b & 1) << 2));

    float acc[2][4][4];
#pragma unroll
    for (int i = 0; i < 2; i++)
#pragma unroll
        for (int j = 0; j < 4; j++)
#pragma unroll
            for (int q = 0; q < 4; q++) acc[i][j][q] = 0.0f;

    const float* Ab = A + (size_t)(row0 + rA) * SDIM + c8a * 8;
    const float* Bb = Bm + (size_t)(col0 + rB) * SDIM + c8b * 8;

    float4 pA[4], pB[2];

#define LDG_CHUNK(kt)                                                \
    do {                                                             \
        pA[0] = *reinterpret_cast<const float4*>(Ab + (kt));         \
        pA[1] = *reinterpret_cast<const float4*>(Ab + (kt) + 4);     \
        pA[2] = *reinterpret_cast<const float4*>(Ab + (kt) + 8);     \
        pA[3] = *reinterpret_cast<const float4*>(Ab + (kt) + 12);    \
        pB[0] = *reinterpret_cast<const float4*>(Bb + (kt));         \
        pB[1] = *reinterpret_cast<const float4*>(Bb + (kt) + 4);     \
    } while (0)

#define STS_CHUNK(stoff)                                             \
    do {                                                             \
        uint32_t h[4], l[4];                                         \
        _Pragma("unroll")                                            \
        for (int jt = 0; jt < 2; jt++) {                             \
            split8(pA[jt * 2], pA[jt * 2 + 1], h, l);                \
            _Pragma("unroll")                                        \
            for (int j = 0; j < 4; j++) {                            \
                sts32(aSt[jt] + (stoff) + j * 16, h[j]);             \
                sts32(aSt[jt] + (stoff) + 8192u + j * 16, l[j]);     \
            }                                                        \
        }                                                            \
        split8(pB[0], pB[1], h, l);                                  \
        _Pragma("unroll")                                            \
        for (int j = 0; j < 4; j++) {                                \
            sts32(bSt + (stoff) + j * 8, h[j]);                      \
            sts32(bSt + (stoff) + 4096u + j * 8, l[j]);              \
        }                                                            \
    } while (0)

    LDG_CHUNK(0);
    STS_CHUNK(0u);
    __syncthreads();

#pragma unroll 1
    for (int c = 0; c < NCHUNK; c++) {
        if (c + 1 < NCHUNK) LDG_CHUNK((c + 1) * KCHUNK);

        const uint32_t s0 = sb + (uint32_t)((c & 1) * STAGE_B);
#pragma unroll
        for (int kb = 0; kb < 2; kb++) {
            uint32_t ah[2][4], al[2][4];
#pragma unroll
            for (int bm = 0; bm < 2; bm++) {
                uint32_t ab = s0 + (uint32_t)((((wm * 2 + bm) * 2 + kb) << 9) + (lid << 4));
                lds128(ah[bm], ab);
                lds128(al[bm], ab + 8192u);
            }
            uint32_t bh[4][2], bl[4][2];
#pragma unroll
            for (int bn = 0; bn < 4; bn++) {
                uint32_t bb = s0 + 16384u + (uint32_t)((((wn * 4 + bn) * 2 + kb) << 8) + (lid << 3));
                lds64(bh[bn], bb);
                lds64(bl[bn], bb + 4096u);
            }
#pragma unroll
            for (int bm = 0; bm < 2; bm++)
#pragma unroll
                for (int bn = 0; bn < 4; bn++)
                    mma16816(acc[bm][bn], ah[bm], bh[bn]);
#pragma unroll
            for (int bm = 0; bm < 2; bm++)
#pragma unroll
                for (int bn = 0; bn < 4; bn++)
                    mma16816(acc[bm][bn], ah[bm], bl[bn]);
#pragma unroll
            for (int bm = 0; bm < 2; bm++)
#pragma unroll
                for (int bn = 0; bn < 4; bn++)
                    mma16816(acc[bm][bn], al[bm], bh[bn]);
        }

        if (c + 1 < NCHUNK) STS_CHUNK((uint32_t)(((c + 1) & 1) * STAGE_B));
        __syncthreads();
    }

    // ---- epilogue ----
    const float invL = (EPI == 2) ? g_scal[0] : 0.0f;
    const float th   = (EPI == 2) ? g_scal[1] : 0.0f;
    const bool mirror = SYM && ((bxi >> 1) != byi);
    const int gid = lid >> 2, tig = lid & 3;
#pragma unroll
    for (int bm = 0; bm < 2; bm++) {
#pragma unroll
        for (int bn = 0; bn < 4; bn++) {
            const int n = col0 + wn * 32 + bn * 8 + tig * 2;
#pragma unroll
            for (int hr = 0; hr < 2; hr++) {
                const int m = row0 + wm * 32 + bm * 16 + gid + hr * 8;
                float ax = acc[bm][bn][hr * 2 + 0];
                float ay = acc[bm][bn][hr * 2 + 1];
                const size_t idx = (size_t)m * SDIM + n;
                if (EPI == 0) {
                    ax *= scale; ay *= scale;
                    float2 o; o.x = ax; o.y = ay;
                    *reinterpret_cast<float2*>(C + idx) = o;
                    if (mirror) {
                        C[(size_t)n * SDIM + m]       = ax;
                        C[(size_t)(n + 1) * SDIM + m] = ay;
                    }
                } else if (EPI == 1) {
                    float2 s  = *reinterpret_cast<const float2*>(src + idx);
                    float2 yv = *reinterpret_cast<const float2*>(Yg + idx);
                    float2 yd = *reinterpret_cast<const float2*>(ydl + idx);
                    float2 rr2, uu;
                    rr2.x = yv.x - s.x * ax - yd.x;  uu.x = s.x * rr2.x;
                    rr2.y = yv.y - s.y * ay - yd.y;  uu.y = s.y * rr2.y;
                    *reinterpret_cast<float2*>(resv + idx) = rr2;
                    *reinterpret_cast<float2*>(uv + idx)   = uu;
                } else {
                    float2 yt = *reinterpret_cast<const float2*>(yth + idx);
                    float2 xt = *reinterpret_cast<const float2*>(xth + idx);
                    float2 xn, yn;
                    xn.x = softthr(yt.x + ax * invL, th);  yn.x = xn.x + mom * (xn.x - xt.x);
                    xn.y = softthr(yt.y + ay * invL, th);  yn.y = xn.y + mom * (xn.y - xt.y);
                    *reinterpret_cast<float2*>(xth + idx) = xn;
                    *reinterpret_cast<float2*>(yth + idx) = yn;
                    float2 rs = *reinterpret_cast<const float2*>(resv + idx);
                    float2 yd = *reinterpret_cast<const float2*>(ydl + idx);
                    float2 xd = *reinterpret_cast<const float2*>(xdl + idx);
                    float2 xnd, ynd;
                    xnd.x = softthr(yd.x + rs.x * invL, th);  ynd.x = xnd.x + mom * (xnd.x - xd.x);
                    xnd.y = softthr(yd.y + rs.y * invL, th);  ynd.y = xnd.y + mom * (xnd.y - xd.y);
                    *reinterpret_cast<float2*>(xdl + idx) = xnd;
                    *reinterpret_cast<float2*>(ydl + idx) = ynd;
                    if (outp) {
                        const size_t ob = (size_t)m * (2 * SDIM) + n;
                        *reinterpret_cast<float2*>(outp + ob)        = xn;
                        *reinterpret_cast<float2*>(outp + ob + SDIM) = xnd;
                    }
                }
            }
        }
    }
}

// ---------------- helper kernels ----------------
__global__ void transpose_kernel(const float* __restrict__ in, float* __restrict__ out) {
    __shared__ float t[32][33];
    int bx = blockIdx.x * 32, by = blockIdx.y * 32;
    int x = bx + threadIdx.x;
#pragma unroll
    for (int i = threadIdx.y; i < 32; i += 8)
        t[i][threadIdx.x] = in[(size_t)(by + i) * SDIM + x];
    __syncthreads();
    int x2 = by + threadIdx.x;
#pragma unroll
    for (int i = threadIdx.y; i < 32; i += 8)
        out[(size_t)(bx + i) * SDIM + x2] = t[threadIdx.x][i];
}

__global__ void fill_kernel() {
    int i = blockIdx.x * blockDim.x + threadIdx.x;
    if (i < SDIM) {
        unsigned h = (unsigned)i * 2654435761u;
        h ^= h >> 13; h *= 2246822519u; h ^= h >> 16;
        g_vec[i] = (float)(h & 0xFFFF) / 65536.0f - 0.5f;
    }
}

__global__ void matvec_kernel(const float* __restrict__ H,
                              const float* __restrict__ x,
                              float* __restrict__ y) {
    int row = blockIdx.x;
    const float* hr = H + (size_t)row * SDIM;
    float s = 0.0f;
    for (int j = threadIdx.x; j < SDIM; j += 256) s += hr[j] * x[j];
#pragma unroll
    for (int o = 16; o > 0; o >>= 1) s += __shfl_xor_sync(0xffffffffu, s, o);
    __shared__ float part[8];
    int w = threadIdx.x >> 5;
    if ((threadIdx.x & 31) == 0) part[w] = s;
    __syncthreads();
    if (threadIdx.x == 0) {
        float t = 0.0f;
#pragma unroll
        for (int k = 0; k < 8; k++) t += part[k];
        y[row] = t;
    }
}

__global__ void normalize_kernel(const float* __restrict__ w, float* __restrict__ v) {
    float ss = 0.0f;
    for (int i = threadIdx.x; i < SDIM; i += 256) { float t = w[i]; ss += t * t; }
#pragma unroll
    for (int o = 16; o > 0; o >>= 1) ss += __shfl_xor_sync(0xffffffffu, ss, o);
    __shared__ float part[8];
    __shared__ float s_inv;
    int wd = threadIdx.x >> 5;
    if ((threadIdx.x & 31) == 0) part[wd] = ss;
    __syncthreads();
    if (threadIdx.x == 0) {
        float t = 0.0f;
        for (int i = 0; i < 8; i++) t += part[i];
        s_inv = rsqrtf(t);
    }
    __syncthreads();
    float inv = s_inv;
    for (int i = threadIdx.x; i < SDIM; i += 256) v[i] = w[i] * inv;
}

// Rayleigh on G'^64 (G' = G/4): L = 4 * lam^(1/64); writes 1/L and thresh.
__global__ void finalize_kernel(const float* __restrict__ v,
                                const float* __restrict__ w,
                                const float* __restrict__ alpha) {
    float num = 0.0f, den = 0.0f;
    for (int i = threadIdx.x; i < SDIM; i += 256) { num += v[i] * w[i]; den += v[i] * v[i]; }
#pragma unroll
    for (int o = 16; o > 0; o >>= 1) {
        num += __shfl_xor_sync(0xffffffffu, num, o);
        den += __shfl_xor_sync(0xffffffffu, den, o);
    }
    __shared__ float pn[8], pd[8];
    int wd = threadIdx.x >> 5;
    if ((threadIdx.x & 31) == 0) { pn[wd] = num; pd[wd] = den; }
    __syncthreads();
    if (threadIdx.x == 0) {
        double n = 0.0, d = 0.0;
        for (int i = 0; i < 8; i++) { n += pn[i]; d += pd[i]; }
        double lam = n / d;
        double L = 4.0 * pow(lam, 1.0 / 64.0);
        g_scal[0] = (float)(1.0 / L);
        g_scal[1] = (float)((double)alpha[0] * 0.5 / L);
    }
}

#define EPI_NULLS nullptr, nullptr, nullptr, nullptr, nullptr, nullptr, nullptr, nullptr, nullptr, 0.0f
#define NSYMT 272   // triangular tiles: sum_{by=0..15} 2*(by+1)

extern "C" void kernel_launch(void* const* d_in, const int* in_sizes, int n_in,
                              void* d_out, int out_size) {
    (void)in_sizes; (void)n_in; (void)out_size;
    const float* src   = (const float*)d_in[0];
    const float* Y     = (const float*)d_in[1];
    const float* W     = (const float*)d_in[2];
    const float* alpha = (const float*)d_in[3];
    float* out = (float*)d_out;

    float *yth, *ydl, *xth, *xdl, *u, *res, *WT, *MA, *MB, *vec, *wvec;
    cudaGetSymbolAddress((void**)&yth,  g_yth);
    cudaGetSymbolAddress((void**)&ydl,  g_ydl);
    cudaGetSymbolAddress((void**)&xth,  g_xth);
    cudaGetSymbolAddress((void**)&xdl,  g_xdl);
    cudaGetSymbolAddress((void**)&u,    g_u);
    cudaGetSymbolAddress((void**)&res,  g_res);
    cudaGetSymbolAddress((void**)&WT,   g_WT);
    cudaGetSymbolAddress((void**)&MA,   g_MA);
    cudaGetSymbolAddress((void**)&MB,   g_MB);
    cudaGetSymbolAddress((void**)&vec,  g_vec);
    cudaGetSymbolAddress((void**)&wvec, g_wvec);

    cudaFuncSetAttribute(mma_gemm<0,1>, cudaFuncAttributeMaxDynamicSharedMemorySize, SMEM_TOTAL);
    cudaFuncSetAttribute(mma_gemm<1,0>, cudaFuncAttributeMaxDynamicSharedMemorySize, SMEM_TOTAL);
    cudaFuncSetAttribute(mma_gemm<2,0>, cudaFuncAttributeMaxDynamicSharedMemorySize, SMEM_TOTAL);

    dim3 ga(SDIM / 64, BATCH / 128);   // 32 x 8 = 256 CTAs (FISTA GEMMs)

    // WT = W^T
    transpose_kernel<<<dim3(64, 64), dim3(32, 8)>>>(W, WT);

    // eigen chain (all outputs symmetric -> triangular grid + mirror):
    // G' = (W^T W)/4, then 6 squarings -> G'^64 in MA
    mma_gemm<0,1><<<NSYMT, NTHREADS, SMEM_TOTAL>>>(WT, WT, MA, 0.25f, EPI_NULLS);
    mma_gemm<0,1><<<NSYMT, NTHREADS, SMEM_TOTAL>>>(MA, MA, MB, 1.0f, EPI_NULLS);
    mma_gemm<0,1><<<NSYMT, NTHREADS, SMEM_TOTAL>>>(MB, MB, MA, 1.0f, EPI_NULLS);
    mma_gemm<0,1><<<NSYMT, NTHREADS, SMEM_TOTAL>>>(MA, MA, MB, 1.0f, EPI_NULLS);
    mma_gemm<0,1><<<NSYMT, NTHREADS, SMEM_TOTAL>>>(MB, MB, MA, 1.0f, EPI_NULLS);
    mma_gemm<0,1><<<NSYMT, NTHREADS, SMEM_TOTAL>>>(MA, MA, MB, 1.0f, EPI_NULLS);
    mma_gemm<0,1><<<NSYMT, NTHREADS, SMEM_TOTAL>>>(MB, MB, MA, 1.0f, EPI_NULLS);

    // power iteration + Rayleigh on G'^64
    fill_kernel<<<(SDIM + 255) / 256, 256>>>();
    for (int i = 0; i < PITERS; i++) {
        matvec_kernel<<<SDIM, 256>>>(MA, vec, wvec);
        normalize_kernel<<<1, 256>>>(wvec, vec);
    }
    matvec_kernel<<<SDIM, 256>>>(MA, vec, wvec);
    finalize_kernel<<<1, 256>>>(vec, wvec, alpha);

    // FISTA state init (x0 = y0 = 0)
    size_t bytes = (size_t)BATCH * SDIM * sizeof(float);
    cudaMemsetAsync(yth, 0, bytes);
    cudaMemsetAsync(ydl, 0, bytes);
    cudaMemsetAsync(xth, 0, bytes);
    cudaMemsetAsync(xdl, 0, bytes);

    float t = 1.0f;
    for (int it = 0; it < N_ITER; it++) {
        float tn  = (1.0f + sqrtf(1.0f + 4.0f * t * t)) * 0.5f;
        float mom = (t - 1.0f) / tn;
        t = tn;
        float* op = (it == N_ITER - 1) ? out : nullptr;

        // Z = yth * W^T ; res = Y - src*Z - ydl ; u = src*res
        mma_gemm<1,0><<<ga, NTHREADS, SMEM_TOTAL>>>(yth, W, nullptr, 0.0f,
            src, Y, res, u, nullptr, nullptr, nullptr, ydl, nullptr, 0.0f);
        // g = W^T u ; theta/delta soft-threshold + momentum (+ out)
        mma_gemm<2,0><<<ga, NTHREADS, SMEM_TOTAL>>>(u, WT, nullptr, 0.0f,
            nullptr, nullptr, res, nullptr, xth, yth, xdl, ydl, op, mom);
    }
}

// round 6
// speedup vs baseline: 2.6930x; 2.6930x over previous
#include <cuda_runtime.h>
#include <math.h>
#include <stdint.h>

#define BATCH   1024
#define SDIM    2048
#define N_ITER  16
#define PITERS  24
#define KCHUNK  32
#define NCHUNK  (SDIM / KCHUNK)    // 64
#define NTHREADS 256

// ---------------- static device scratch ----------------
__device__ __align__(256) float g_yth[BATCH * SDIM];
__device__ __align__(256) float g_ydl[BATCH * SDIM];
__device__ __align__(256) float g_xth[BATCH * SDIM];
__device__ __align__(256) float g_xdl[BATCH * SDIM];
__device__ __align__(256) float g_u  [BATCH * SDIM];
__device__ __align__(256) float g_res[BATCH * SDIM];
__device__ __align__(256) float g_WT [SDIM * SDIM];
__device__ __align__(256) float g_MA [SDIM * SDIM];
__device__ __align__(256) float g_MB [SDIM * SDIM];
__device__ __align__(256) float g_vec [SDIM];
__device__ __align__(256) float g_wvec[SDIM];
__device__ float g_scal[4];   // [0] = 1/L, [1] = thresh

// SMEM per stage: Ahi[0,8K) Alo[8K,16K) Bhi[16K,24K) Blo[24K,32K)
// A layout: [mt 8][kb 2][wi 4][lane 32] words ; B: [nt 16][kb 2][wi 2][lane 32]
#define AHI_OFF 0
#define ALO_OFF 8192
#define BHI_OFF 16384
#define BLO_OFF 24576
#define STAGE_B    32768
#define SMEM_TOTAL (2 * STAGE_B)   // 64 KB

static __device__ __forceinline__ uint32_t smem_u32(const void* p) {
    uint32_t a;
    asm("{ .reg .u64 t; cvta.to.shared.u64 t, %1; cvt.u32.u64 %0, t; }" : "=r"(a) : "l"(p));
    return a;
}
static __device__ __forceinline__ uint32_t lds32(uint32_t a) {
    uint32_t v; asm volatile("ld.shared.b32 %0, [%1];" : "=r"(v) : "r"(a)); return v;
}
static __device__ __forceinline__ void sts64(uint32_t a, uint32_t v0, uint32_t v1) {
    asm volatile("st.shared.v2.b32 [%0], {%1,%2};" :: "r"(a), "r"(v0), "r"(v1));
}
static __device__ __forceinline__ void mma16816(float* d, const uint32_t* a, const uint32_t* b) {
    asm volatile(
        "mma.sync.aligned.m16n8k16.row.col.f32.bf16.bf16.f32 "
        "{%0,%1,%2,%3}, {%4,%5,%6,%7}, {%8,%9}, {%0,%1,%2,%3};"
        : "+f"(d[0]), "+f"(d[1]), "+f"(d[2]), "+f"(d[3])
        : "r"(a[0]), "r"(a[1]), "r"(a[2]), "r"(a[3]), "r"(b[0]), "r"(b[1]));
}

// split float4 -> 2 packed bf16x2 hi (truncated) + 2 lo (rounded residual)
static __device__ __forceinline__ void split4(float4 v, uint32_t& h0, uint32_t& h1,
                                              uint32_t& l0, uint32_t& l1) {
    uint32_t u0 = __float_as_uint(v.x), u1 = __float_as_uint(v.y);
    uint32_t u2 = __float_as_uint(v.z), u3 = __float_as_uint(v.w);
    h0 = __byte_perm(u0, u1, 0x7632);
    h1 = __byte_perm(u2, u3, 0x7632);
    float a0 = v.x - __uint_as_float(u0 & 0xFFFF0000u);
    float a1 = v.y - __uint_as_float(u1 & 0xFFFF0000u);
    float a2 = v.z - __uint_as_float(u2 & 0xFFFF0000u);
    float a3 = v.w - __uint_as_float(u3 & 0xFFFF0000u);
    asm("cvt.rn.bf16x2.f32 %0, %1, %2;" : "=r"(l0) : "f"(a1), "f"(a0));
    asm("cvt.rn.bf16x2.f32 %0, %1, %2;" : "=r"(l1) : "f"(a3), "f"(a2));
}

static __device__ __forceinline__ float softthr(float v, float th) {
    float a = fabsf(v) - th;
    return a > 0.0f ? copysignf(a, v) : 0.0f;
}

// ---------------------------------------------------------------------------
// C[m,n] = sum_k A[m,k]*B[n,k], K=2048. CTA tile 128x128, 8 warps (4x2),
// warp tile 32x64 (bm=2 m16-tiles, bn=8 n8-tiles).
// SYM=1: triangular grid over 128x128 tiles (by>=bx) + mirrored write.
// EPI 0: C=acc*scale   EPI 1: res/u   EPI 2: FISTA update (+out)
// ---------------------------------------------------------------------------
template<int EPI, int SYM>
__global__ void __launch_bounds__(NTHREADS)
mma_gemm(const float* __restrict__ A, const float* __restrict__ Bm,
         float* __restrict__ C, float scale,
         const float* __restrict__ src, const float* __restrict__ Yg,
         float* __restrict__ resv, float* __restrict__ uv,
         float* __restrict__ xth, float* __restrict__ yth,
         float* __restrict__ xdl, float* __restrict__ ydl,
         float* __restrict__ outp, float mom)
{
    extern __shared__ char smem[];
    const uint32_t sb = smem_u32(smem);
    const int tid = threadIdx.x;
    const int wid = tid >> 5, lid = tid & 31;
    const int wm = wid & 3, wn = wid >> 2;   // 4 x 2 warps over (M, N)

    int row0, col0;
    bool mirror = false;
    if (SYM) {
        int t = blockIdx.x;
        int by = (int)((sqrtf(8.0f * t + 1.0f) - 1.0f) * 0.5f);
        while ((by + 1) * (by + 2) / 2 <= t) by++;
        while (by * (by + 1) / 2 > t) by--;
        int bx = t - by * (by + 1) / 2;   // 0..by
        row0 = by * 128; col0 = bx * 128;
        mirror = (bx != by);
    } else {
        row0 = blockIdx.y * 128; col0 = blockIdx.x * 128;
    }

    // ---- producer mapping: coalesced LDG, conflict-free STS.64 ----
    // thread: rows rbase+32p (p=0..3), cols qa*4..qa*4+3 of the k-chunk
    const int qa = tid & 7;
    const int rbase = tid >> 3;              // 0..31
    const int kbp = qa >> 2;                 // k16 index within chunk
    const int hp  = (qa >> 1) & 1;           // k8 half within k16
    const int q1  = qa & 1;
    uint32_t aOff[4], bOff[4];
#pragma unroll
    for (int p = 0; p < 4; p++) {
        int r = rbase + 32 * p;
        int mt = r >> 4, rr = r & 15, rrq = rr & 7, r8 = rr >> 3;
        int blkA = (mt * 2 + kbp) * 4 + hp * 2 + r8;
        aOff[p] = (uint32_t)((blkA * 32 + rrq * 4 + 2 * q1) * 4);
        int nt = r >> 3, nn = r & 7;
        int blkB = (nt * 2 + kbp) * 2 + hp;
        bOff[p] = (uint32_t)((blkB * 32 + nn * 4 + 2 * q1) * 4);
    }
    const float* Abase = A  + (size_t)(row0 + rbase) * SDIM + qa * 4;
    const float* Bbase = Bm + (size_t)(col0 + rbase) * SDIM + qa * 4;

    float acc[2][8][4];
#pragma unroll
    for (int i = 0; i < 2; i++)
#pragma unroll
        for (int j = 0; j < 8; j++)
#pragma unroll
            for (int q = 0; q < 4; q++) acc[i][j][q] = 0.0f;

    float4 pA[4], pB[4];

#define LDG_CHUNK(kt)                                                              \
    do {                                                                           \
        _Pragma("unroll")                                                          \
        for (int p = 0; p < 4; p++) {                                              \
            pA[p] = *reinterpret_cast<const float4*>(Abase + (size_t)(32 * p) * SDIM + (kt)); \
            pB[p] = *reinterpret_cast<const float4*>(Bbase + (size_t)(32 * p) * SDIM + (kt)); \
        }                                                                          \
    } while (0)

#define STS_CHUNK(stoff)                                                           \
    do {                                                                           \
        _Pragma("unroll")                                                          \
        for (int p = 0; p < 4; p++) {                                              \
            uint32_t h0, h1, l0, l1;                                               \
            split4(pA[p], h0, h1, l0, l1);                                         \
            sts64(sb + (stoff) + AHI_OFF + aOff[p], h0, h1);                       \
            sts64(sb + (stoff) + ALO_OFF + aOff[p], l0, l1);                       \
            split4(pB[p], h0, h1, l0, l1);                                         \
            sts64(sb + (stoff) + BHI_OFF + bOff[p], h0, h1);                       \
            sts64(sb + (stoff) + BLO_OFF + bOff[p], l0, l1);                       \
        }                                                                          \
    } while (0)

    LDG_CHUNK(0);
    STS_CHUNK(0u);
    __syncthreads();

    const uint32_t l4 = (uint32_t)(lid * 4);

#pragma unroll 1
    for (int c = 0; c < NCHUNK; c++) {
        if (c + 1 < NCHUNK) LDG_CHUNK((c + 1) * KCHUNK);

        const uint32_t s0 = sb + (uint32_t)((c & 1) * STAGE_B);
#pragma unroll
        for (int kb = 0; kb < 2; kb++) {
            uint32_t ah[2][4], al[2][4];
#pragma unroll
            for (int bm = 0; bm < 2; bm++) {
                int mt = wm * 2 + bm;
                uint32_t ab = s0 + (uint32_t)(((mt * 2 + kb) * 4) * 128) + l4;
#pragma unroll
                for (int wi = 0; wi < 4; wi++) {
                    ah[bm][wi] = lds32(ab + AHI_OFF + wi * 128);
                    al[bm][wi] = lds32(ab + ALO_OFF + wi * 128);
                }
            }
#pragma unroll
            for (int half = 0; half < 2; half++) {
                uint32_t bh[4][2], bl[4][2];
#pragma unroll
                for (int j = 0; j < 4; j++) {
                    int nt = wn * 8 + half * 4 + j;
                    uint32_t bb = s0 + (uint32_t)(((nt * 2 + kb) * 2) * 128) + l4;
                    bh[j][0] = lds32(bb + BHI_OFF);
                    bh[j][1] = lds32(bb + BHI_OFF + 128);
                    bl[j][0] = lds32(bb + BLO_OFF);
                    bl[j][1] = lds32(bb + BLO_OFF + 128);
                }
                // three passes: each accumulator revisited after 8 other MMAs
#pragma unroll
                for (int bm = 0; bm < 2; bm++)
#pragma unroll
                    for (int j = 0; j < 4; j++)
                        mma16816(acc[bm][half * 4 + j], ah[bm], bh[j]);
#pragma unroll
                for (int bm = 0; bm < 2; bm++)
#pragma unroll
                    for (int j = 0; j < 4; j++)
                        mma16816(acc[bm][half * 4 + j], ah[bm], bl[j]);
#pragma unroll
                for (int bm = 0; bm < 2; bm++)
#pragma unroll
                    for (int j = 0; j < 4; j++)
                        mma16816(acc[bm][half * 4 + j], al[bm], bh[j]);
            }
        }

        if (c + 1 < NCHUNK) STS_CHUNK((uint32_t)(((c + 1) & 1) * STAGE_B));
        __syncthreads();
    }

    // ---- epilogue ----
    const float invL = (EPI == 2) ? g_scal[0] : 0.0f;
    const float th   = (EPI == 2) ? g_scal[1] : 0.0f;
    const int gid = lid >> 2, tig = lid & 3;
#pragma unroll
    for (int bm = 0; bm < 2; bm++) {
#pragma unroll
        for (int bn = 0; bn < 8; bn++) {
            const int n = col0 + wn * 64 + bn * 8 + tig * 2;
#pragma unroll
            for (int hr = 0; hr < 2; hr++) {
                const int m = row0 + wm * 32 + bm * 16 + gid + hr * 8;
                float ax = acc[bm][bn][hr * 2 + 0];
                float ay = acc[bm][bn][hr * 2 + 1];
                const size_t idx = (size_t)m * SDIM + n;
                if (EPI == 0) {
                    ax *= scale; ay *= scale;
                    float2 o; o.x = ax; o.y = ay;
                    *reinterpret_cast<float2*>(C + idx) = o;
                    if (SYM && mirror) {
                        C[(size_t)n * SDIM + m]       = ax;
                        C[(size_t)(n + 1) * SDIM + m] = ay;
                    }
                } else if (EPI == 1) {
                    float2 s  = *reinterpret_cast<const float2*>(src + idx);
                    float2 yv = *reinterpret_cast<const float2*>(Yg + idx);
                    float2 yd = *reinterpret_cast<const float2*>(ydl + idx);
                    float2 rr2, uu;
                    rr2.x = yv.x - s.x * ax - yd.x;  uu.x = s.x * rr2.x;
                    rr2.y = yv.y - s.y * ay - yd.y;  uu.y = s.y * rr2.y;
                    *reinterpret_cast<float2*>(resv + idx) = rr2;
                    *reinterpret_cast<float2*>(uv + idx)   = uu;
                } else {
                    float2 yt = *reinterpret_cast<const float2*>(yth + idx);
                    float2 xt = *reinterpret_cast<const float2*>(xth + idx);
                    float2 xn, yn;
                    xn.x = softthr(yt.x + ax * invL, th);  yn.x = xn.x + mom * (xn.x - xt.x);
                    xn.y = softthr(yt.y + ay * invL, th);  yn.y = xn.y + mom * (xn.y - xt.y);
                    *reinterpret_cast<float2*>(xth + idx) = xn;
                    *reinterpret_cast<float2*>(yth + idx) = yn;
                    float2 rs = *reinterpret_cast<const float2*>(resv + idx);
                    float2 yd = *reinterpret_cast<const float2*>(ydl + idx);
                    float2 xd = *reinterpret_cast<const float2*>(xdl + idx);
                    float2 xnd, ynd;
                    xnd.x = softthr(yd.x + rs.x * invL, th);  ynd.x = xnd.x + mom * (xnd.x - xd.x);
                    xnd.y = softthr(yd.y + rs.y * invL, th);  ynd.y = xnd.y + mom * (xnd.y - xd.y);
                    *reinterpret_cast<float2*>(xdl + idx) = xnd;
                    *reinterpret_cast<float2*>(ydl + idx) = ynd;
                    if (outp) {
                        const size_t ob = (size_t)m * (2 * SDIM) + n;
                        *reinterpret_cast<float2*>(outp + ob)        = xn;
                        *reinterpret_cast<float2*>(outp + ob + SDIM) = xnd;
                    }
                }
            }
        }
    }
}

// ---------------- helper kernels ----------------
__global__ void transpose_kernel(const float* __restrict__ in, float* __restrict__ out) {
    __shared__ float t[32][33];
    int bx = blockIdx.x * 32, by = blockIdx.y * 32;
    int x = bx + threadIdx.x;
#pragma unroll
    for (int i = threadIdx.y; i < 32; i += 8)
        t[i][threadIdx.x] = in[(size_t)(by + i) * SDIM + x];
    __syncthreads();
    int x2 = by + threadIdx.x;
#pragma unroll
    for (int i = threadIdx.y; i < 32; i += 8)
        out[(size_t)(bx + i) * SDIM + x2] = t[threadIdx.x][i];
}

__global__ void fill_kernel() {
    int i = blockIdx.x * blockDim.x + threadIdx.x;
    if (i < SDIM) {
        unsigned h = (unsigned)i * 2654435761u;
        h ^= h >> 13; h *= 2246822519u; h ^= h >> 16;
        g_vec[i] = (float)(h & 0xFFFF) / 65536.0f - 0.5f;
    }
}

__global__ void matvec_kernel(const float* __restrict__ H,
                              const float* __restrict__ x,
                              float* __restrict__ y) {
    int row = blockIdx.x;
    const float* hr = H + (size_t)row * SDIM;
    float s = 0.0f;
    for (int j = threadIdx.x; j < SDIM; j += 256) s += hr[j] * x[j];
#pragma unroll
    for (int o = 16; o > 0; o >>= 1) s += __shfl_xor_sync(0xffffffffu, s, o);
    __shared__ float part[8];
    int w = threadIdx.x >> 5;
    if ((threadIdx.x & 31) == 0) part[w] = s;
    __syncthreads();
    if (threadIdx.x == 0) {
        float t = 0.0f;
#pragma unroll
        for (int k = 0; k < 8; k++) t += part[k];
        y[row] = t;
    }
}

__global__ void normalize_kernel(const float* __restrict__ w, float* __restrict__ v) {
    float ss = 0.0f;
    for (int i = threadIdx.x; i < SDIM; i += 256) { float t = w[i]; ss += t * t; }
#pragma unroll
    for (int o = 16; o > 0; o >>= 1) ss += __shfl_xor_sync(0xffffffffu, ss, o);
    __shared__ float part[8];
    __shared__ float s_inv;
    int wd = threadIdx.x >> 5;
    if ((threadIdx.x & 31) == 0) part[wd] = ss;
    __syncthreads();
    if (threadIdx.x == 0) {
        float t = 0.0f;
        for (int i = 0; i < 8; i++) t += part[i];
        s_inv = rsqrtf(t);
    }
    __syncthreads();
    float inv = s_inv;
    for (int i = threadIdx.x; i < SDIM; i += 256) v[i] = w[i] * inv;
}

// Rayleigh on G'^64 (G' = G/4): L = 4 * lam^(1/64); writes 1/L and thresh.
__global__ void finalize_kernel(const float* __restrict__ v,
                                const float* __restrict__ w,
                                const float* __restrict__ alpha) {
    float num = 0.0f, den = 0.0f;
    for (int i = threadIdx.x; i < SDIM; i += 256) { num += v[i] * w[i]; den += v[i] * v[i]; }
#pragma unroll
    for (int o = 16; o > 0; o >>= 1) {
        num += __shfl_xor_sync(0xffffffffu, num, o);
        den += __shfl_xor_sync(0xffffffffu, den, o);
    }
    __shared__ float pn[8], pd[8];
    int wd = threadIdx.x >> 5;
    if ((threadIdx.x & 31) == 0) { pn[wd] = num; pd[wd] = den; }
    __syncthreads();
    if (threadIdx.x == 0) {
        double n = 0.0, d = 0.0;
        for (int i = 0; i < 8; i++) { n += pn[i]; d += pd[i]; }
        double lam = n / d;
        double L = 4.0 * pow(lam, 1.0 / 64.0);
        g_scal[0] = (float)(1.0 / L);
        g_scal[1] = (float)((double)alpha[0] * 0.5 / L);
    }
}

#define EPI_NULLS nullptr, nullptr, nullptr, nullptr, nullptr, nullptr, nullptr, nullptr, nullptr, 0.0f
#define NSYMT 136   // triangular 128x128 tiles: 16*17/2

extern "C" void kernel_launch(void* const* d_in, const int* in_sizes, int n_in,
                              void* d_out, int out_size) {
    (void)in_sizes; (void)n_in; (void)out_size;
    const float* src   = (const float*)d_in[0];
    const float* Y     = (const float*)d_in[1];
    const float* W     = (const float*)d_in[2];
    const float* alpha = (const float*)d_in[3];
    float* out = (float*)d_out;

    float *yth, *ydl, *xth, *xdl, *u, *res, *WT, *MA, *MB, *vec, *wvec;
    cudaGetSymbolAddress((void**)&yth,  g_yth);
    cudaGetSymbolAddress((void**)&ydl,  g_ydl);
    cudaGetSymbolAddress((void**)&xth,  g_xth);
    cudaGetSymbolAddress((void**)&xdl,  g_xdl);
    cudaGetSymbolAddress((void**)&u,    g_u);
    cudaGetSymbolAddress((void**)&res,  g_res);
    cudaGetSymbolAddress((void**)&WT,   g_WT);
    cudaGetSymbolAddress((void**)&MA,   g_MA);
    cudaGetSymbolAddress((void**)&MB,   g_MB);
    cudaGetSymbolAddress((void**)&vec,  g_vec);
    cudaGetSymbolAddress((void**)&wvec, g_wvec);

    cudaFuncSetAttribute(mma_gemm<0,1>, cudaFuncAttributeMaxDynamicSharedMemorySize, SMEM_TOTAL);
    cudaFuncSetAttribute(mma_gemm<1,0>, cudaFuncAttributeMaxDynamicSharedMemorySize, SMEM_TOTAL);
    cudaFuncSetAttribute(mma_gemm<2,0>, cudaFuncAttributeMaxDynamicSharedMemorySize, SMEM_TOTAL);

    dim3 ga(SDIM / 128, BATCH / 128);   // 16 x 8 = 128 CTAs (FISTA GEMMs)

    // WT = W^T
    transpose_kernel<<<dim3(64, 64), dim3(32, 8)>>>(W, WT);

    // eigen chain (symmetric outputs -> triangular grid + mirror):
    // G' = (W^T W)/4, then 6 squarings -> G'^64 in MA
    mma_gemm<0,1><<<NSYMT, NTHREADS, SMEM_TOTAL>>>(WT, WT, MA, 0.25f, EPI_NULLS);
    mma_gemm<0,1><<<NSYMT, NTHREADS, SMEM_TOTAL>>>(MA, MA, MB, 1.0f, EPI_NULLS);
    mma_gemm<0,1><<<NSYMT, NTHREADS, SMEM_TOTAL>>>(MB, MB, MA, 1.0f, EPI_NULLS);
    mma_gemm<0,1><<<NSYMT, NTHREADS, SMEM_TOTAL>>>(MA, MA, MB, 1.0f, EPI_NULLS);
    mma_gemm<0,1><<<NSYMT, NTHREADS, SMEM_TOTAL>>>(MB, MB, MA, 1.0f, EPI_NULLS);
    mma_gemm<0,1><<<NSYMT, NTHREADS, SMEM_TOTAL>>>(MA, MA, MB, 1.0f, EPI_NULLS);
    mma_gemm<0,1><<<NSYMT, NTHREADS, SMEM_TOTAL>>>(MB, MB, MA, 1.0f, EPI_NULLS);

    // power iteration + Rayleigh on G'^64
    fill_kernel<<<(SDIM + 255) / 256, 256>>>();
    for (int i = 0; i < PITERS; i++) {
        matvec_kernel<<<SDIM, 256>>>(MA, vec, wvec);
        normalize_kernel<<<1, 256>>>(wvec, vec);
    }
    matvec_kernel<<<SDIM, 256>>>(MA, vec, wvec);
    finalize_kernel<<<1, 256>>>(vec, wvec, alpha);

    // FISTA state init (x0 = y0 = 0)
    size_t bytes = (size_t)BATCH * SDIM * sizeof(float);
    cudaMemsetAsync(yth, 0, bytes);
    cudaMemsetAsync(ydl, 0, bytes);
    cudaMemsetAsync(xth, 0, bytes);
    cudaMemsetAsync(xdl, 0, bytes);

    float t = 1.0f;
    for (int it = 0; it < N_ITER; it++) {
        float tn  = (1.0f + sqrtf(1.0f + 4.0f * t * t)) * 0.5f;
        float mom = (t - 1.0f) / tn;
        t = tn;
        float* op = (it == N_ITER - 1) ? out : nullptr;

        // Z = yth * W^T ; res = Y - src*Z - ydl ; u = src*res
        mma_gemm<1,0><<<ga, NTHREADS, SMEM_TOTAL>>>(yth, W, nullptr, 0.0f,
            src, Y, res, u, nullptr, nullptr, nullptr, ydl, nullptr, 0.0f);
        // g = W^T u ; theta/delta soft-threshold + momentum (+ out)
        mma_gemm<2,0><<<ga, NTHREADS, SMEM_TOTAL>>>(u, WT, nullptr, 0.0f,
            nullptr, nullptr, res, nullptr, xth, yth, xdl, ydl, op, mom);
    }
}

// round 7
// speedup vs baseline: 3.1811x; 1.1813x over previous
#include <cuda_runtime.h>
#include <math.h>
#include <stdint.h>

#define BATCH   1024
#define SDIM    2048
#define N_ITER  16
#define KCHUNK  32
#define NCHUNK  (SDIM / KCHUNK)    // 64
#define NTHREADS 256

// ---------------- static device scratch ----------------
__device__ __align__(256) float g_yth[BATCH * SDIM];
__device__ __align__(256) float g_ydl[BATCH * SDIM];
__device__ __align__(256) float g_xth[BATCH * SDIM];
__device__ __align__(256) float g_xdl[BATCH * SDIM];
__device__ __align__(256) float g_u  [BATCH * SDIM];
__device__ __align__(256) float g_res[BATCH * SDIM];
__device__ __align__(256) float g_WT [SDIM * SDIM];
__device__ __align__(256) float g_MA [SDIM * SDIM];
__device__ __align__(256) float g_MB [SDIM * SDIM];
__device__ __align__(256) float g_vec [SDIM];
__device__ __align__(256) float g_wvec[SDIM];
__device__ float g_scal[4];   // [0] = 1/L, [1] = thresh

// SMEM per stage: Ahi[0,8K) Alo[8K,16K) Bhi[16K,20K) Blo[20K,24K)
// A layout: [mt 8][kb 2][wi 4][lane 32] words ; B: [nt 8][kb 2][wi 2][lane 32]
#define AHI_OFF 0
#define ALO_OFF 8192
#define BHI_OFF 16384
#define BLO_OFF 20480
#define STAGE_B    24576
#define SMEM_TOTAL (2 * STAGE_B)   // 48 KB -> 2 CTAs/SM

static __device__ __forceinline__ uint32_t smem_u32(const void* p) {
    uint32_t a;
    asm("{ .reg .u64 t; cvta.to.shared.u64 t, %1; cvt.u32.u64 %0, t; }" : "=r"(a) : "l"(p));
    return a;
}
static __device__ __forceinline__ uint32_t lds32(uint32_t a) {
    uint32_t v; asm volatile("ld.shared.b32 %0, [%1];" : "=r"(v) : "r"(a)); return v;
}
static __device__ __forceinline__ void sts64(uint32_t a, uint32_t v0, uint32_t v1) {
    asm volatile("st.shared.v2.b32 [%0], {%1,%2};" :: "r"(a), "r"(v0), "r"(v1));
}
static __device__ __forceinline__ void mma16816(float* d, const uint32_t* a, const uint32_t* b) {
    asm volatile(
        "mma.sync.aligned.m16n8k16.row.col.f32.bf16.bf16.f32 "
        "{%0,%1,%2,%3}, {%4,%5,%6,%7}, {%8,%9}, {%0,%1,%2,%3};"
        : "+f"(d[0]), "+f"(d[1]), "+f"(d[2]), "+f"(d[3])
        : "r"(a[0]), "r"(a[1]), "r"(a[2]), "r"(a[3]), "r"(b[0]), "r"(b[1]));
}

// split float4 -> 2 packed bf16x2 hi (truncated) + 2 lo (rounded residual)
static __device__ __forceinline__ void split4(float4 v, uint32_t& h0, uint32_t& h1,
                                              uint32_t& l0, uint32_t& l1) {
    uint32_t u0 = __float_as_uint(v.x), u1 = __float_as_uint(v.y);
    uint32_t u2 = __float_as_uint(v.z), u3 = __float_as_uint(v.w);
    h0 = __byte_perm(u0, u1, 0x7632);
    h1 = __byte_perm(u2, u3, 0x7632);
    float a0 = v.x - __uint_as_float(u0 & 0xFFFF0000u);
    float a1 = v.y - __uint_as_float(u1 & 0xFFFF0000u);
    float a2 = v.z - __uint_as_float(u2 & 0xFFFF0000u);
    float a3 = v.w - __uint_as_float(u3 & 0xFFFF0000u);
    asm("cvt.rn.bf16x2.f32 %0, %1, %2;" : "=r"(l0) : "f"(a1), "f"(a0));
    asm("cvt.rn.bf16x2.f32 %0, %1, %2;" : "=r"(l1) : "f"(a3), "f"(a2));
}

static __device__ __forceinline__ float softthr(float v, float th) {
    float a = fabsf(v) - th;
    return a > 0.0f ? copysignf(a, v) : 0.0f;
}

// ---------------------------------------------------------------------------
// C[m,n] = sum_k A[m,k]*B[n,k], K=2048. CTA tile 128(M)x64(N), 8 warps (4x2),
// warp tile 32x32 (bm=2 m16-tiles, bn=4 n8-tiles). 2 CTAs/SM.
// SYM=1: triangular grid over (128-row, 64-col) tiles + mirrored write.
// EPI 0: C=acc*scale   EPI 1: res/u   EPI 2: FISTA update (+out)
// ---------------------------------------------------------------------------
template<int EPI, int SYM>
__global__ void __launch_bounds__(NTHREADS, 2)
mma_gemm(const float* __restrict__ A, const float* __restrict__ Bm,
         float* __restrict__ C, float scale,
         const float* __restrict__ src, const float* __restrict__ Yg,
         float* __restrict__ resv, float* __restrict__ uv,
         float* __restrict__ xth, float* __restrict__ yth,
         float* __restrict__ xdl, float* __restrict__ ydl,
         float* __restrict__ outp, float mom)
{
    extern __shared__ char smem[];
    const uint32_t sb = smem_u32(smem);
    const int tid = threadIdx.x;
    const int wid = tid >> 5, lid = tid & 31;
    const int wm = wid & 3, wn = wid >> 2;   // 4 x 2 warps over (M, N)

    int row0, col0;
    bool mirror = false;
    if (SYM) {
        int t = blockIdx.x;
        int by = (int)((sqrtf(4.0f * t + 1.0f) - 1.0f) * 0.5f);
        while ((by + 1) * (by + 2) <= t) by++;
        while (by * (by + 1) > t) by--;
        int bx = t - by * (by + 1);      // 0 .. 2*by+1
        row0 = by * 128; col0 = bx * 64;
        mirror = ((bx >> 1) != by);
    } else {
        row0 = blockIdx.y * 128; col0 = blockIdx.x * 64;
    }

    // ---- producer mapping: coalesced LDG, conflict-free STS.64 ----
    const int qa = tid & 7;
    const int rbase = tid >> 3;              // 0..31
    const int kbp = qa >> 2;                 // k16 index within chunk
    const int hp  = (qa >> 1) & 1;           // k8 half within k16
    const int q1  = qa & 1;
    uint32_t aOff[4], bOff[2];
#pragma unroll
    for (int p = 0; p < 4; p++) {
        int r = rbase + 32 * p;
        int mt = r >> 4, rr = r & 15, rrq = rr & 7, r8 = rr >> 3;
        int blkA = (mt * 2 + kbp) * 4 + hp * 2 + r8;
        aOff[p] = (uint32_t)((blkA * 32 + rrq * 4 + 2 * q1) * 4);
    }
#pragma unroll
    for (int p = 0; p < 2; p++) {
        int r = rbase + 32 * p;
        int nt = r >> 3, nn = r & 7;
        int blkB = (nt * 2 + kbp) * 2 + hp;
        bOff[p] = (uint32_t)((blkB * 32 + nn * 4 + 2 * q1) * 4);
    }
    const float* Abase = A  + (size_t)(row0 + rbase) * SDIM + qa * 4;
    const float* Bbase = Bm + (size_t)(col0 + rbase) * SDIM + qa * 4;

    float acc[2][4][4];
#pragma unroll
    for (int i = 0; i < 2; i++)
#pragma unroll
        for (int j = 0; j < 4; j++)
#pragma unroll
            for (int q = 0; q < 4; q++) acc[i][j][q] = 0.0f;

    float4 pA[4], pB[2];

#define LDG_CHUNK(kt)                                                              \
    do {                                                                           \
        _Pragma("unroll")                                                          \
        for (int p = 0; p < 4; p++)                                                \
            pA[p] = *reinterpret_cast<const float4*>(Abase + (size_t)(32 * p) * SDIM + (kt)); \
        _Pragma("unroll")                                                          \
        for (int p = 0; p < 2; p++)                                                \
            pB[p] = *reinterpret_cast<const float4*>(Bbase + (size_t)(32 * p) * SDIM + (kt)); \
    } while (0)

#define STS_CHUNK(stoff)                                                           \
    do {                                                                           \
        _Pragma("unroll")                                                          \
        for (int p = 0; p < 4; p++) {                                              \
            uint32_t h0, h1, l0, l1;                                               \
            split4(pA[p], h0, h1, l0, l1);                                         \
            sts64(sb + (stoff) + AHI_OFF + aOff[p], h0, h1);                       \
            sts64(sb + (stoff) + ALO_OFF + aOff[p], l0, l1);                       \
        }                                                                          \
        _Pragma("unroll")                                                          \
        for (int p = 0; p < 2; p++) {                                              \
            uint32_t h0, h1, l0, l1;                                               \
            split4(pB[p], h0, h1, l0, l1);                                         \
            sts64(sb + (stoff) + BHI_OFF + bOff[p], h0, h1);                       \
            sts64(sb + (stoff) + BLO_OFF + bOff[p], l0, l1);                       \
        }                                                                          \
    } while (0)

    LDG_CHUNK(0);
    STS_CHUNK(0u);
    __syncthreads();

    const uint32_t l4 = (uint32_t)(lid * 4);

#pragma unroll 1
    for (int c = 0; c < NCHUNK; c++) {
        if (c + 1 < NCHUNK) LDG_CHUNK((c + 1) * KCHUNK);

        const uint32_t s0 = sb + (uint32_t)((c & 1) * STAGE_B);
#pragma unroll
        for (int kb = 0; kb < 2; kb++) {
            uint32_t ah[2][4], al[2][4];
#pragma unroll
            for (int bm = 0; bm < 2; bm++) {
                int mt = wm * 2 + bm;
                uint32_t ab = s0 + (uint32_t)(((mt * 2 + kb) * 4) * 128) + l4;
#pragma unroll
                for (int wi = 0; wi < 4; wi++) {
                    ah[bm][wi] = lds32(ab + AHI_OFF + wi * 128);
                    al[bm][wi] = lds32(ab + ALO_OFF + wi * 128);
                }
            }
            uint32_t bh[4][2], bl[4][2];
#pragma unroll
            for (int j = 0; j < 4; j++) {
                int nt = wn * 4 + j;
                uint32_t bb = s0 + (uint32_t)(((nt * 2 + kb) * 2) * 128) + l4;
                bh[j][0] = lds32(bb + BHI_OFF);
                bh[j][1] = lds32(bb + BHI_OFF + 128);
                bl[j][0] = lds32(bb + BLO_OFF);
                bl[j][1] = lds32(bb + BLO_OFF + 128);
            }
            // three passes: each accumulator revisited after 8 other MMAs
#pragma unroll
            for (int bm = 0; bm < 2; bm++)
#pragma unroll
                for (int j = 0; j < 4; j++)
                    mma16816(acc[bm][j], ah[bm], bh[j]);
#pragma unroll
            for (int bm = 0; bm < 2; bm++)
#pragma unroll
                for (int j = 0; j < 4; j++)
                    mma16816(acc[bm][j], ah[bm], bl[j]);
#pragma unroll
            for (int bm = 0; bm < 2; bm++)
#pragma unroll
                for (int j = 0; j < 4; j++)
                    mma16816(acc[bm][j], al[bm], bh[j]);
        }

        if (c + 1 < NCHUNK) STS_CHUNK((uint32_t)(((c + 1) & 1) * STAGE_B));
        __syncthreads();
    }

    // ---- epilogue ----
    const float invL = (EPI == 2) ? g_scal[0] : 0.0f;
    const float th   = (EPI == 2) ? g_scal[1] : 0.0f;
    const int gid = lid >> 2, tig = lid & 3;
#pragma unroll
    for (int bm = 0; bm < 2; bm++) {
#pragma unroll
        for (int bn = 0; bn < 4; bn++) {
            const int n = col0 + wn * 32 + bn * 8 + tig * 2;
#pragma unroll
            for (int hr = 0; hr < 2; hr++) {
                const int m = row0 + wm * 32 + bm * 16 + gid + hr * 8;
                float ax = acc[bm][bn][hr * 2 + 0];
                float ay = acc[bm][bn][hr * 2 + 1];
                const size_t idx = (size_t)m * SDIM + n;
                if (EPI == 0) {
                    ax *= scale; ay *= scale;
                    float2 o; o.x = ax; o.y = ay;
                    *reinterpret_cast<float2*>(C + idx) = o;
                    if (SYM && mirror) {
                        C[(size_t)n * SDIM + m]       = ax;
                        C[(size_t)(n + 1) * SDIM + m] = ay;
                    }
                } else if (EPI == 1) {
                    float2 s  = *reinterpret_cast<const float2*>(src + idx);
                    float2 yv = *reinterpret_cast<const float2*>(Yg + idx);
                    float2 yd = *reinterpret_cast<const float2*>(ydl + idx);
                    float2 rr2, uu;
                    rr2.x = yv.x - s.x * ax - yd.x;  uu.x = s.x * rr2.x;
                    rr2.y = yv.y - s.y * ay - yd.y;  uu.y = s.y * rr2.y;
                    *reinterpret_cast<float2*>(resv + idx) = rr2;
                    *reinterpret_cast<float2*>(uv + idx)   = uu;
                } else {
                    float2 yt = *reinterpret_cast<const float2*>(yth + idx);
                    float2 xt = *reinterpret_cast<const float2*>(xth + idx);
                    float2 xn, yn;
                    xn.x = softthr(yt.x + ax * invL, th);  yn.x = xn.x + mom * (xn.x - xt.x);
                    xn.y = softthr(yt.y + ay * invL, th);  yn.y = xn.y + mom * (xn.y - xt.y);
                    *reinterpret_cast<float2*>(xth + idx) = xn;
                    *reinterpret_cast<float2*>(yth + idx) = yn;
                    float2 rs = *reinterpret_cast<const float2*>(resv + idx);
                    float2 yd = *reinterpret_cast<const float2*>(ydl + idx);
                    float2 xd = *reinterpret_cast<const float2*>(xdl + idx);
                    float2 xnd, ynd;
                    xnd.x = softthr(yd.x + rs.x * invL, th);  ynd.x = xnd.x + mom * (xnd.x - xd.x);
                    xnd.y = softthr(yd.y + rs.y * invL, th);  ynd.y = xnd.y + mom * (xnd.y - xd.y);
                    *reinterpret_cast<float2*>(xdl + idx) = xnd;
                    *reinterpret_cast<float2*>(ydl + idx) = ynd;
                    if (outp) {
                        const size_t ob = (size_t)m * (2 * SDIM) + n;
                        *reinterpret_cast<float2*>(outp + ob)        = xn;
                        *reinterpret_cast<float2*>(outp + ob + SDIM) = xnd;
                    }
                }
            }
        }
    }
}

// ---------------- helper kernels ----------------
__global__ void transpose_kernel(const float* __restrict__ in, float* __restrict__ out) {
    __shared__ float t[32][33];
    int bx = blockIdx.x * 32, by = blockIdx.y * 32;
    int x = bx + threadIdx.x;
#pragma unroll
    for (int i = threadIdx.y; i < 32; i += 8)
        t[i][threadIdx.x] = in[(size_t)(by + i) * SDIM + x];
    __syncthreads();
    int x2 = by + threadIdx.x;
#pragma unroll
    for (int i = threadIdx.y; i < 32; i += 8)
        out[(size_t)(bx + i) * SDIM + x2] = t[threadIdx.x][i];
}

__global__ void fill_kernel() {
    int i = blockIdx.x * blockDim.x + threadIdx.x;
    if (i < SDIM) {
        unsigned h = (unsigned)i * 2654435761u;
        h ^= h >> 13; h *= 2246822519u; h ^= h >> 16;
        g_vec[i] = (float)(h & 0xFFFF) / 65536.0f - 0.5f;
    }
}

__global__ void matvec_kernel(const float* __restrict__ H,
                              const float* __restrict__ x,
                              float* __restrict__ y) {
    int row = blockIdx.x;
    const float* hr = H + (size_t)row * SDIM;
    float s = 0.0f;
    for (int j = threadIdx.x; j < SDIM; j += 256) s += hr[j] * x[j];
#pragma unroll
    for (int o = 16; o > 0; o >>= 1) s += __shfl_xor_sync(0xffffffffu, s, o);
    __shared__ float part[8];
    int w = threadIdx.x >> 5;
    if ((threadIdx.x & 31) == 0) part[w] = s;
    __syncthreads();
    if (threadIdx.x == 0) {
        float t = 0.0f;
#pragma unroll
        for (int k = 0; k < 8; k++) t += part[k];
        y[row] = t;
    }
}

__global__ void normalize_kernel(const float* __restrict__ w, float* __restrict__ v) {
    float ss = 0.0f;
    for (int i = threadIdx.x; i < SDIM; i += 256) { float t = w[i]; ss += t * t; }
#pragma unroll
    for (int o = 16; o > 0; o >>= 1) ss += __shfl_xor_sync(0xffffffffu, ss, o);
    __shared__ float part[8];
    __shared__ float s_inv;
    int wd = threadIdx.x >> 5;
    if ((threadIdx.x & 31) == 0) part[wd] = ss;
    __syncthreads();
    if (threadIdx.x == 0) {
        float t = 0.0f;
        for (int i = 0; i < 8; i++) t += part[i];
        s_inv = rsqrtf(t);
    }
    __syncthreads();
    float inv = s_inv;
    for (int i = threadIdx.x; i < SDIM; i += 256) v[i] = w[i] * inv;
}

// Rayleigh on G'^64 (G' = G/4): L = 4 * lam^(1/64); writes 1/L and thresh.
__global__ void finalize_kernel(const float* __restrict__ v,
                                const float* __restrict__ w,
                                const float* __restrict__ alpha) {
    float num = 0.0f, den = 0.0f;
    for (int i = threadIdx.x; i < SDIM; i += 256) { num += v[i] * w[i]; den += v[i] * v[i]; }
#pragma unroll
    for (int o = 16; o > 0; o >>= 1) {
        num += __shfl_xor_sync(0xffffffffu, num, o);
        den += __shfl_xor_sync(0xffffffffu, den, o);
    }
    __shared__ float pn[8], pd[8];
    int wd = threadIdx.x >> 5;
    if ((threadIdx.x & 31) == 0) { pn[wd] = num; pd[wd] = den; }
    __syncthreads();
    if (threadIdx.x == 0) {
        double n = 0.0, d = 0.0;
        for (int i = 0; i < 8; i++) { n += pn[i]; d += pd[i]; }
        double lam = n / d;
        double L = 4.0 * pow(lam, 1.0 / 64.0);
        g_scal[0] = (float)(1.0 / L);
        g_scal[1] = (float)((double)alpha[0] * 0.5 / L);
    }
}

#define EPI_NULLS nullptr, nullptr, nullptr, nullptr, nullptr, nullptr, nullptr, nullptr, nullptr, 0.0f
#define NSYMT 272   // triangular (128-row x 64-col) tiles: sum_{by=0..15} 2*(by+1)

extern "C" void kernel_launch(void* const* d_in, const int* in_sizes, int n_in,
                              void* d_out, int out_size) {
    (void)in_sizes; (void)n_in; (void)out_size;
    const float* src   = (const float*)d_in[0];
    const float* Y     = (const float*)d_in[1];
    const float* W     = (const float*)d_in[2];
    const float* alpha = (const float*)d_in[3];
    float* out = (float*)d_out;

    float *yth, *ydl, *xth, *xdl, *u, *res, *WT, *MA, *MB, *vec, *wvec;
    cudaGetSymbolAddress((void**)&yth,  g_yth);
    cudaGetSymbolAddress((void**)&ydl,  g_ydl);
    cudaGetSymbolAddress((void**)&xth,  g_xth);
    cudaGetSymbolAddress((void**)&xdl,  g_xdl);
    cudaGetSymbolAddress((void**)&u,    g_u);
    cudaGetSymbolAddress((void**)&res,  g_res);
    cudaGetSymbolAddress((void**)&WT,   g_WT);
    cudaGetSymbolAddress((void**)&MA,   g_MA);
    cudaGetSymbolAddress((void**)&MB,   g_MB);
    cudaGetSymbolAddress((void**)&vec,  g_vec);
    cudaGetSymbolAddress((void**)&wvec, g_wvec);

    cudaFuncSetAttribute(mma_gemm<0,1>, cudaFuncAttributeMaxDynamicSharedMemorySize, SMEM_TOTAL);
    cudaFuncSetAttribute(mma_gemm<1,0>, cudaFuncAttributeMaxDynamicSharedMemorySize, SMEM_TOTAL);
    cudaFuncSetAttribute(mma_gemm<2,0>, cudaFuncAttributeMaxDynamicSharedMemorySize, SMEM_TOTAL);

    dim3 ga(SDIM / 64, BATCH / 128);   // 32 x 8 = 256 CTAs (FISTA GEMMs)

    // WT = W^T
    transpose_kernel<<<dim3(64, 64), dim3(32, 8)>>>(W, WT);

    // eigen chain (symmetric outputs -> triangular grid + mirror):
    // G' = (W^T W)/4, then 6 squarings -> G'^64 in MA
    mma_gemm<0,1><<<NSYMT, NTHREADS, SMEM_TOTAL>>>(WT, WT, MA, 0.25f, EPI_NULLS);
    mma_gemm<0,1><<<NSYMT, NTHREADS, SMEM_TOTAL>>>(MA, MA, MB, 1.0f, EPI_NULLS);
    mma_gemm<0,1><<<NSYMT, NTHREADS, SMEM_TOTAL>>>(MB, MB, MA, 1.0f, EPI_NULLS);
    mma_gemm<0,1><<<NSYMT, NTHREADS, SMEM_TOTAL>>>(MA, MA, MB, 1.0f, EPI_NULLS);
    mma_gemm<0,1><<<NSYMT, NTHREADS, SMEM_TOTAL>>>(MB, MB, MA, 1.0f, EPI_NULLS);
    mma_gemm<0,1><<<NSYMT, NTHREADS, SMEM_TOTAL>>>(MA, MA, MB, 1.0f, EPI_NULLS);
    mma_gemm<0,1><<<NSYMT, NTHREADS, SMEM_TOTAL>>>(MB, MB, MA, 1.0f, EPI_NULLS);

    // power iteration + Rayleigh on G'^64: 16 matvecs, normalize every 8
    fill_kernel<<<(SDIM + 255) / 256, 256>>>();
    for (int i = 0; i < 2; i++) {
        for (int jj = 0; jj < 7; jj++) {
            matvec_kernel<<<SDIM, 256>>>(MA, vec, wvec);
            float* tmp = vec; vec = wvec; wvec = tmp;
        }
        matvec_kernel<<<SDIM, 256>>>(MA, vec, wvec);
        normalize_kernel<<<1, 256>>>(wvec, vec);
    }
    matvec_kernel<<<SDIM, 256>>>(MA, vec, wvec);
    finalize_kernel<<<1, 256>>>(vec, wvec, alpha);

    // FISTA state init (x0 = y0 = 0)
    size_t bytes = (size_t)BATCH * SDIM * sizeof(float);
    cudaMemsetAsync(yth, 0, bytes);
    cudaMemsetAsync(ydl, 0, bytes);
    cudaMemsetAsync(xth, 0, bytes);
    cudaMemsetAsync(xdl, 0, bytes);

    float t = 1.0f;
    for (int it = 0; it < N_ITER; it++) {
        float tn  = (1.0f + sqrtf(1.0f + 4.0f * t * t)) * 0.5f;
        float mom = (t - 1.0f) / tn;
        t = tn;
        float* op = (it == N_ITER - 1) ? out : nullptr;

        // Z = yth * W^T ; res = Y - src*Z - ydl ; u = src*res
        mma_gemm<1,0><<<ga, NTHREADS, SMEM_TOTAL>>>(yth, W, nullptr, 0.0f,
            src, Y, res, u, nullptr, nullptr, nullptr, ydl, nullptr, 0.0f);
        // g = W^T u ; theta/delta soft-threshold + momentum (+ out)
        mma_gemm<2,0><<<ga, NTHREADS, SMEM_TOTAL>>>(u, WT, nullptr, 0.0f,
            nullptr, nullptr, res, nullptr, xth, yth, xdl, ydl, op, mom);
    }
}

// round 8
// speedup vs baseline: 3.6350x; 1.1427x over previous
#include <cuda_runtime.h>
#include <math.h>
#include <stdint.h>

#define BATCH   1024
#define SDIM    2048
#define N_ITER  16
#define KCHUNK  16
#define NCHUNK  (SDIM / KCHUNK)    // 128
#define NTHREADS 128

// ---------------- static device scratch ----------------
__device__ __align__(256) float g_yth[BATCH * SDIM];
__device__ __align__(256) float g_ydl[BATCH * SDIM];
__device__ __align__(256) float g_xth[BATCH * SDIM];
__device__ __align__(256) float g_xdl[BATCH * SDIM];
__device__ __align__(256) float g_u  [BATCH * SDIM];
__device__ __align__(256) float g_res[BATCH * SDIM];
__device__ __align__(256) float g_WT [SDIM * SDIM];
__device__ __align__(256) float g_MA [SDIM * SDIM];
__device__ __align__(256) float g_MB [SDIM * SDIM];
__device__ __align__(256) float g_vec [SDIM];
__device__ __align__(256) float g_wvec[SDIM];
__device__ float g_scal[4];   // [0] = 1/L, [1] = thresh

// SMEM per stage: Ahi[0,2K) Alo[2K,4K) Bhi[4K,8K) Blo[8K,12K)
// A: [mt 4][wi 4][lane 32] words ; B: [nt 16][wi 2][lane 32]
#define AHI_OFF 0
#define ALO_OFF 2048
#define BHI_OFF 4096
#define BLO_OFF 8192
#define STAGE_B    12288
#define SMEM_TOTAL (2 * STAGE_B)   // 24 KB -> multi-CTA/SM

static __device__ __forceinline__ uint32_t smem_u32(const void* p) {
    uint32_t a;
    asm("{ .reg .u64 t; cvta.to.shared.u64 t, %1; cvt.u32.u64 %0, t; }" : "=r"(a) : "l"(p));
    return a;
}
static __device__ __forceinline__ uint32_t lds32(uint32_t a) {
    uint32_t v; asm volatile("ld.shared.b32 %0, [%1];" : "=r"(v) : "r"(a)); return v;
}
static __device__ __forceinline__ void sts64(uint32_t a, uint32_t v0, uint32_t v1) {
    asm volatile("st.shared.v2.b32 [%0], {%1,%2};" :: "r"(a), "r"(v0), "r"(v1));
}
static __device__ __forceinline__ void mma16816(float* d, const uint32_t* a, const uint32_t* b) {
    asm volatile(
        "mma.sync.aligned.m16n8k16.row.col.f32.bf16.bf16.f32 "
        "{%0,%1,%2,%3}, {%4,%5,%6,%7}, {%8,%9}, {%0,%1,%2,%3};"
        : "+f"(d[0]), "+f"(d[1]), "+f"(d[2]), "+f"(d[3])
        : "r"(a[0]), "r"(a[1]), "r"(a[2]), "r"(a[3]), "r"(b[0]), "r"(b[1]));
}

// split float4 -> 2 packed bf16x2 hi (truncated) + 2 lo (rounded residual)
static __device__ __forceinline__ void split4(float4 v, uint32_t& h0, uint32_t& h1,
                                              uint32_t& l0, uint32_t& l1) {
    uint32_t u0 = __float_as_uint(v.x), u1 = __float_as_uint(v.y);
    uint32_t u2 = __float_as_uint(v.z), u3 = __float_as_uint(v.w);
    h0 = __byte_perm(u0, u1, 0x7632);
    h1 = __byte_perm(u2, u3, 0x7632);
    float a0 = v.x - __uint_as_float(u0 & 0xFFFF0000u);
    float a1 = v.y - __uint_as_float(u1 & 0xFFFF0000u);
    float a2 = v.z - __uint_as_float(u2 & 0xFFFF0000u);
    float a3 = v.w - __uint_as_float(u3 & 0xFFFF0000u);
    asm("cvt.rn.bf16x2.f32 %0, %1, %2;" : "=r"(l0) : "f"(a1), "f"(a0));
    asm("cvt.rn.bf16x2.f32 %0, %1, %2;" : "=r"(l1) : "f"(a3), "f"(a2));
}

static __device__ __forceinline__ float softthr(float v, float th) {
    float a = fabsf(v) - th;
    return a > 0.0f ? copysignf(a, v) : 0.0f;
}

// ---------------------------------------------------------------------------
// C[m,n] = sum_k A[m,k]*B[n,k], K=2048. CTA tile 64(M)x128(N), 4 warps (2x2),
// warp tile 32x64 (bm=2 m16-tiles, bn=8 n8-tiles). KCHUNK=16, 2 stages.
// SYM=1: 1D grid: 136 triangular 128x128 macros x 2 half-tiles; mirror write.
// EPI 0: C=acc*scale   EPI 1: res/u   EPI 2: FISTA update (+out)
// ---------------------------------------------------------------------------
template<int EPI, int SYM>
__global__ void __launch_bounds__(NTHREADS, 3)
mma_gemm(const float* __restrict__ A, const float* __restrict__ Bm,
         float* __restrict__ C, float scale,
         const float* __restrict__ src, const float* __restrict__ Yg,
         float* __restrict__ resv, float* __restrict__ uv,
         float* __restrict__ xth, float* __restrict__ yth,
         float* __restrict__ xdl, float* __restrict__ ydl,
         float* __restrict__ outp, float mom)
{
    extern __shared__ char smem[];
    const uint32_t sb = smem_u32(smem);
    const int tid = threadIdx.x;
    const int wid = tid >> 5, lid = tid & 31;
    const int wm = wid & 1, wn = wid >> 1;   // 2 x 2 warps over (M, N)

    int row0, col0;
    bool mirror = false;
    if (SYM) {
        int bid = blockIdx.x;
        int mac = bid >> 1, half = bid & 1;
        int by = (int)((sqrtf(8.0f * mac + 1.0f) - 1.0f) * 0.5f);
        while ((by + 1) * (by + 2) / 2 <= mac) by++;
        while (by * (by + 1) / 2 > mac) by--;
        int bx = mac - by * (by + 1) / 2;   // 0..by
        row0 = by * 128 + half * 64;
        col0 = bx * 128;
        mirror = (bx != by);
    } else {
        row0 = blockIdx.y * 64; col0 = blockIdx.x * 128;
    }

    // ---- producer mapping: coalesced LDG, conflict-free STS.64 ----
    const int qa = tid & 3;                  // 4-col group within 16-col chunk
    const int rbase = tid >> 2;              // 0..31
    const int hp = qa >> 1;                  // k8 half
    const int q1 = qa & 1;                   // kpair pair within k8
    uint32_t aOff[2], bOff[4];
#pragma unroll
    for (int p = 0; p < 2; p++) {
        int r = rbase + 32 * p;              // 0..63
        int mt = r >> 4, rr = r & 15, rrq = rr & 7, r8 = rr >> 3;
        aOff[p] = (uint32_t)(((mt * 4 + hp * 2 + r8) * 32 + rrq * 4 + 2 * q1) * 4);
    }
#pragma unroll
    for (int p = 0; p < 4; p++) {
        int r = rbase + 32 * p;              // 0..127
        int nt = r >> 3, nn = r & 7;
        bOff[p] = (uint32_t)(((nt * 2 + hp) * 32 + nn * 4 + 2 * q1) * 4);
    }
    const float* Abase = A  + (size_t)(row0 + rbase) * SDIM + qa * 4;
    const float* Bbase = Bm + (size_t)(col0 + rbase) * SDIM + qa * 4;

    float acc[2][8][4];
#pragma unroll
    for (int i = 0; i < 2; i++)
#pragma unroll
        for (int j = 0; j < 8; j++)
#pragma unroll
            for (int q = 0; q < 4; q++) acc[i][j][q] = 0.0f;

    float4 pA[2], pB[4];

#define LDG_CHUNK(kt)                                                              \
    do {                                                                           \
        _Pragma("unroll")                                                          \
        for (int p = 0; p < 2; p++)                                                \
            pA[p] = *reinterpret_cast<const float4*>(Abase + (size_t)(32 * p) * SDIM + (kt)); \
        _Pragma("unroll")                                                          \
        for (int p = 0; p < 4; p++)                                                \
            pB[p] = *reinterpret_cast<const float4*>(Bbase + (size_t)(32 * p) * SDIM + (kt)); \
    } while (0)

#define STS_CHUNK(stoff)                                                           \
    do {                                                                           \
        _Pragma("unroll")                                                          \
        for (int p = 0; p < 2; p++) {                                              \
            uint32_t h0, h1, l0, l1;                                               \
            split4(pA[p], h0, h1, l0, l1);                                         \
            sts64(sb + (stoff) + AHI_OFF + aOff[p], h0, h1);                       \
            sts64(sb + (stoff) + ALO_OFF + aOff[p], l0, l1);                       \
        }                                                                          \
        _Pragma("unroll")                                                          \
        for (int p = 0; p < 4; p++) {                                              \
            uint32_t h0, h1, l0, l1;                                               \
            split4(pB[p], h0, h1, l0, l1);                                         \
            sts64(sb + (stoff) + BHI_OFF + bOff[p], h0, h1);                       \
            sts64(sb + (stoff) + BLO_OFF + bOff[p], l0, l1);                       \
        }                                                                          \
    } while (0)

    LDG_CHUNK(0);
    STS_CHUNK(0u);
    __syncthreads();

    const uint32_t l4 = (uint32_t)(lid * 4);

#pragma unroll 1
    for (int c = 0; c < NCHUNK; c++) {
        if (c + 1 < NCHUNK) LDG_CHUNK((c + 1) * KCHUNK);

        const uint32_t s0 = sb + (uint32_t)((c & 1) * STAGE_B);
        uint32_t ah[2][4], al[2][4];
#pragma unroll
        for (int bm = 0; bm < 2; bm++) {
            int mt = wm * 2 + bm;
            uint32_t ab = s0 + (uint32_t)((mt * 4) * 128) + l4;
#pragma unroll
            for (int wi = 0; wi < 4; wi++) {
                ah[bm][wi] = lds32(ab + AHI_OFF + wi * 128);
                al[bm][wi] = lds32(ab + ALO_OFF + wi * 128);
            }
        }
#pragma unroll
        for (int half = 0; half < 2; half++) {
            uint32_t bh[4][2], bl[4][2];
#pragma unroll
            for (int j = 0; j < 4; j++) {
                int nt = wn * 8 + half * 4 + j;
                uint32_t bb = s0 + (uint32_t)((nt * 2) * 128) + l4;
                bh[j][0] = lds32(bb + BHI_OFF);
                bh[j][1] = lds32(bb + BHI_OFF + 128);
                bl[j][0] = lds32(bb + BLO_OFF);
                bl[j][1] = lds32(bb + BLO_OFF + 128);
            }
            // three passes: accumulator revisited after 8 other MMAs
#pragma unroll
            for (int bm = 0; bm < 2; bm++)
#pragma unroll
                for (int j = 0; j < 4; j++)
                    mma16816(acc[bm][half * 4 + j], ah[bm], bh[j]);
#pragma unroll
            for (int bm = 0; bm < 2; bm++)
#pragma unroll
                for (int j = 0; j < 4; j++)
                    mma16816(acc[bm][half * 4 + j], ah[bm], bl[j]);
#pragma unroll
            for (int bm = 0; bm < 2; bm++)
#pragma unroll
                for (int j = 0; j < 4; j++)
                    mma16816(acc[bm][half * 4 + j], al[bm], bh[j]);
        }

        if (c + 1 < NCHUNK) STS_CHUNK((uint32_t)(((c + 1) & 1) * STAGE_B));
        __syncthreads();
    }

    // ---- epilogue ----
    const float invL = (EPI == 2) ? g_scal[0] : 0.0f;
    const float th   = (EPI == 2) ? g_scal[1] : 0.0f;
    const int gid = lid >> 2, tig = lid & 3;
#pragma unroll
    for (int bm = 0; bm < 2; bm++) {
#pragma unroll
        for (int bn = 0; bn < 8; bn++) {
            const int n = col0 + wn * 64 + bn * 8 + tig * 2;
#pragma unroll
            for (int hr = 0; hr < 2; hr++) {
                const int m = row0 + wm * 32 + bm * 16 + gid + hr * 8;
                float ax = acc[bm][bn][hr * 2 + 0];
                float ay = acc[bm][bn][hr * 2 + 1];
                const size_t idx = (size_t)m * SDIM + n;
                if (EPI == 0) {
                    ax *= scale; ay *= scale;
                    float2 o; o.x = ax; o.y = ay;
                    *reinterpret_cast<float2*>(C + idx) = o;
                    if (SYM && mirror) {
                        C[(size_t)n * SDIM + m]       = ax;
                        C[(size_t)(n + 1) * SDIM + m] = ay;
                    }
                } else if (EPI == 1) {
                    float2 s  = *reinterpret_cast<const float2*>(src + idx);
                    float2 yv = *reinterpret_cast<const float2*>(Yg + idx);
                    float2 yd = *reinterpret_cast<const float2*>(ydl + idx);
                    float2 rr2, uu;
                    rr2.x = yv.x - s.x * ax - yd.x;  uu.x = s.x * rr2.x;
                    rr2.y = yv.y - s.y * ay - yd.y;  uu.y = s.y * rr2.y;
                    *reinterpret_cast<float2*>(resv + idx) = rr2;
                    *reinterpret_cast<float2*>(uv + idx)   = uu;
                } else {
                    float2 yt = *reinterpret_cast<const float2*>(yth + idx);
                    float2 xt = *reinterpret_cast<const float2*>(xth + idx);
                    float2 xn, yn;
                    xn.x = softthr(yt.x + ax * invL, th);  yn.x = xn.x + mom * (xn.x - xt.x);
                    xn.y = softthr(yt.y + ay * invL, th);  yn.y = xn.y + mom * (xn.y - xt.y);
                    *reinterpret_cast<float2*>(xth + idx) = xn;
                    *reinterpret_cast<float2*>(yth + idx) = yn;
                    float2 rs = *reinterpret_cast<const float2*>(resv + idx);
                    float2 yd = *reinterpret_cast<const float2*>(ydl + idx);
                    float2 xd = *reinterpret_cast<const float2*>(xdl + idx);
                    float2 xnd, ynd;
                    xnd.x = softthr(yd.x + rs.x * invL, th);  ynd.x = xnd.x + mom * (xnd.x - xd.x);
                    xnd.y = softthr(yd.y + rs.y * invL, th);  ynd.y = xnd.y + mom * (xnd.y - xd.y);
                    *reinterpret_cast<float2*>(xdl + idx) = xnd;
                    *reinterpret_cast<float2*>(ydl + idx) = ynd;
                    if (outp) {
                        const size_t ob = (size_t)m * (2 * SDIM) + n;
                        *reinterpret_cast<float2*>(outp + ob)        = xn;
                        *reinterpret_cast<float2*>(outp + ob + SDIM) = xnd;
                    }
                }
            }
        }
    }
}

// ---------------- helper kernels ----------------
__global__ void transpose_kernel(const float* __restrict__ in, float* __restrict__ out) {
    __shared__ float t[32][33];
    int bx = blockIdx.x * 32, by = blockIdx.y * 32;
    int x = bx + threadIdx.x;
#pragma unroll
    for (int i = threadIdx.y; i < 32; i += 8)
        t[i][threadIdx.x] = in[(size_t)(by + i) * SDIM + x];
    __syncthreads();
    int x2 = by + threadIdx.x;
#pragma unroll
    for (int i = threadIdx.y; i < 32; i += 8)
        out[(size_t)(bx + i) * SDIM + x2] = t[threadIdx.x][i];
}

// iteration-0 GEMM1 shortcut: y=0 -> res = Y, u = src*Y
__global__ void init_iter0_kernel(const float* __restrict__ src, const float* __restrict__ Yg,
                                  float* __restrict__ resv, float* __restrict__ uv) {
    int i = blockIdx.x * blockDim.x + threadIdx.x;
    float4 y = reinterpret_cast<const float4*>(Yg)[i];
    float4 s = reinterpret_cast<const float4*>(src)[i];
    reinterpret_cast<float4*>(resv)[i] = y;
    float4 u; u.x = s.x * y.x; u.y = s.y * y.y; u.z = s.z * y.z; u.w = s.w * y.w;
    reinterpret_cast<float4*>(uv)[i] = u;
}

__global__ void fill_kernel() {
    int i = blockIdx.x * blockDim.x + threadIdx.x;
    if (i < SDIM) {
        unsigned h = (unsigned)i * 2654435761u;
        h ^= h >> 13; h *= 2246822519u; h ^= h >> 16;
        g_vec[i] = (float)(h & 0xFFFF) / 65536.0f - 0.5f;
    }
}

__global__ void matvec_kernel(const float* __restrict__ H,
                              const float* __restrict__ x,
                              float* __restrict__ y) {
    int row = blockIdx.x;
    const float* hr = H + (size_t)row * SDIM;
    float s = 0.0f;
    for (int j = threadIdx.x; j < SDIM; j += 256) s += hr[j] * x[j];
#pragma unroll
    for (int o = 16; o > 0; o >>= 1) s += __shfl_xor_sync(0xffffffffu, s, o);
    __shared__ float part[8];
    int w = threadIdx.x >> 5;
    if ((threadIdx.x & 31) == 0) part[w] = s;
    __syncthreads();
    if (threadIdx.x == 0) {
        float t = 0.0f;
#pragma unroll
        for (int k = 0; k < 8; k++) t += part[k];
        y[row] = t;
    }
}

__global__ void normalize_kernel(const float* __restrict__ w, float* __restrict__ v) {
    float ss = 0.0f;
    for (int i = threadIdx.x; i < SDIM; i += 256) { float t = w[i]; ss += t * t; }
#pragma unroll
    for (int o = 16; o > 0; o >>= 1) ss += __shfl_xor_sync(0xffffffffu, ss, o);
    __shared__ float part[8];
    __shared__ float s_inv;
    int wd = threadIdx.x >> 5;
    if ((threadIdx.x & 31) == 0) part[wd] = ss;
    __syncthreads();
    if (threadIdx.x == 0) {
        float t = 0.0f;
        for (int i = 0; i < 8; i++) t += part[i];
        s_inv = rsqrtf(t);
    }
    __syncthreads();
    float inv = s_inv;
    for (int i = threadIdx.x; i < SDIM; i += 256) v[i] = w[i] * inv;
}

// Rayleigh on G'^64 (G' = G/4): L = 4 * lam^(1/64); writes 1/L and thresh.
__global__ void finalize_kernel(const float* __restrict__ v,
                                const float* __restrict__ w,
                                const float* __restrict__ alpha) {
    float num = 0.0f, den = 0.0f;
    for (int i = threadIdx.x; i < SDIM; i += 256) { num += v[i] * w[i]; den += v[i] * v[i]; }
#pragma unroll
    for (int o = 16; o > 0; o >>= 1) {
        num += __shfl_xor_sync(0xffffffffu, num, o);
        den += __shfl_xor_sync(0xffffffffu, den, o);
    }
    __shared__ float pn[8], pd[8];
    int wd = threadIdx.x >> 5;
    if ((threadIdx.x & 31) == 0) { pn[wd] = num; pd[wd] = den; }
    __syncthreads();
    if (threadIdx.x == 0) {
        double n = 0.0, d = 0.0;
        for (int i = 0; i < 8; i++) { n += pn[i]; d += pd[i]; }
        double lam = n / d;
        double L = 4.0 * pow(lam, 1.0 / 64.0);
        g_scal[0] = (float)(1.0 / L);
        g_scal[1] = (float)((double)alpha[0] * 0.5 / L);
    }
}

#define EPI_NULLS nullptr, nullptr, nullptr, nullptr, nullptr, nullptr, nullptr, nullptr, nullptr, 0.0f
#define NSYMT (136 * 2)   // 136 triangular 128x128 macros x 2 (64-row) half-tiles

extern "C" void kernel_launch(void* const* d_in, const int* in_sizes, int n_in,
                              void* d_out, int out_size) {
    (void)in_sizes; (void)n_in; (void)out_size;
    const float* src   = (const float*)d_in[0];
    const float* Y     = (const float*)d_in[1];
    const float* W     = (const float*)d_in[2];
    const float* alpha = (const float*)d_in[3];
    float* out = (float*)d_out;

    float *yth, *ydl, *xth, *xdl, *u, *res, *WT, *MA, *MB, *vec, *wvec;
    cudaGetSymbolAddress((void**)&yth,  g_yth);
    cudaGetSymbolAddress((void**)&ydl,  g_ydl);
    cudaGetSymbolAddress((void**)&xth,  g_xth);
    cudaGetSymbolAddress((void**)&xdl,  g_xdl);
    cudaGetSymbolAddress((void**)&u,    g_u);
    cudaGetSymbolAddress((void**)&res,  g_res);
    cudaGetSymbolAddress((void**)&WT,   g_WT);
    cudaGetSymbolAddress((void**)&MA,   g_MA);
    cudaGetSymbolAddress((void**)&MB,   g_MB);
    cudaGetSymbolAddress((void**)&vec,  g_vec);
    cudaGetSymbolAddress((void**)&wvec, g_wvec);

    cudaFuncSetAttribute(mma_gemm<0,1>, cudaFuncAttributeMaxDynamicSharedMemorySize, SMEM_TOTAL);
    cudaFuncSetAttribute(mma_gemm<1,0>, cudaFuncAttributeMaxDynamicSharedMemorySize, SMEM_TOTAL);
    cudaFuncSetAttribute(mma_gemm<2,0>, cudaFuncAttributeMaxDynamicSharedMemorySize, SMEM_TOTAL);

    dim3 ga(SDIM / 128, BATCH / 64);   // 16 x 16 = 256 CTAs (FISTA GEMMs)

    // WT = W^T
    transpose_kernel<<<dim3(64, 64), dim3(32, 8)>>>(W, WT);

    // eigen chain (symmetric outputs -> triangular macro grid + mirror):
    // G' = (W^T W)/4, then 6 squarings -> G'^64 in MA
    mma_gemm<0,1><<<NSYMT, NTHREADS, SMEM_TOTAL>>>(WT, WT, MA, 0.25f, EPI_NULLS);
    mma_gemm<0,1><<<NSYMT, NTHREADS, SMEM_TOTAL>>>(MA, MA, MB, 1.0f, EPI_NULLS);
    mma_gemm<0,1><<<NSYMT, NTHREADS, SMEM_TOTAL>>>(MB, MB, MA, 1.0f, EPI_NULLS);
    mma_gemm<0,1><<<NSYMT, NTHREADS, SMEM_TOTAL>>>(MA, MA, MB, 1.0f, EPI_NULLS);
    mma_gemm<0,1><<<NSYMT, NTHREADS, SMEM_TOTAL>>>(MB, MB, MA, 1.0f, EPI_NULLS);
    mma_gemm<0,1><<<NSYMT, NTHREADS, SMEM_TOTAL>>>(MA, MA, MB, 1.0f, EPI_NULLS);
    mma_gemm<0,1><<<NSYMT, NTHREADS, SMEM_TOTAL>>>(MB, MB, MA, 1.0f, EPI_NULLS);

    // power iteration + Rayleigh on G'^64: 17 matvecs, normalize every 8
    fill_kernel<<<(SDIM + 255) / 256, 256>>>();
    for (int i = 0; i < 2; i++) {
        for (int jj = 0; jj < 7; jj++) {
            matvec_kernel<<<SDIM, 256>>>(MA, vec, wvec);
            float* tmp = vec; vec = wvec; wvec = tmp;
        }
        matvec_kernel<<<SDIM, 256>>>(MA, vec, wvec);
        normalize_kernel<<<1, 256>>>(wvec, vec);
    }
    matvec_kernel<<<SDIM, 256>>>(MA, vec, wvec);
    finalize_kernel<<<1, 256>>>(vec, wvec, alpha);

    // FISTA state init (x0 = y0 = 0)
    size_t bytes = (size_t)BATCH * SDIM * sizeof(float);
    cudaMemsetAsync(yth, 0, bytes);
    cudaMemsetAsync(ydl, 0, bytes);
    cudaMemsetAsync(xth, 0, bytes);
    cudaMemsetAsync(xdl, 0, bytes);

    float t = 1.0f;
    for (int it = 0; it < N_ITER; it++) {
        float tn  = (1.0f + sqrtf(1.0f + 4.0f * t * t)) * 0.5f;
        float mom = (t - 1.0f) / tn;
        t = tn;
        float* op = (it == N_ITER - 1) ? out : nullptr;

        if (it == 0) {
            // y0 = 0: res = Y, u = src*Y (skip full GEMM1)
            init_iter0_kernel<<<(BATCH * SDIM / 4 + 255) / 256, 256>>>(src, Y, res, u);
        } else {
            // Z = yth * W^T ; res = Y - src*Z - ydl ; u = src*res
            mma_gemm<1,0><<<ga, NTHREADS, SMEM_TOTAL>>>(yth, W, nullptr, 0.0f,
                src, Y, res, u, nullptr, nullptr, nullptr, ydl, nullptr, 0.0f);
        }
        // g = W^T u ; theta/delta soft-threshold + momentum (+ out)
        mma_gemm<2,0><<<ga, NTHREADS, SMEM_TOTAL>>>(u, WT, nullptr, 0.0f,
            nullptr, nullptr, res, nullptr, xth, yth, xdl, ydl, op, mom);
    }
}

// round 9
// speedup vs baseline: 4.5686x; 1.2568x over previous
#include <cuda_runtime.h>
#include <math.h>
#include <stdint.h>

#define BATCH   1024
#define SDIM    2048
#define N_ITER  16
#define KCHUNK  16
#define NCHUNK  (SDIM / KCHUNK)    // 128
#define NTTILES (SDIM / 8)         // 256

// ---------------- static device scratch ----------------
__device__ __align__(256) float g_yth[BATCH * SDIM];
__device__ __align__(256) float g_ydl[BATCH * SDIM];
__device__ __align__(256) float g_xth[BATCH * SDIM];
__device__ __align__(256) float g_xdl[BATCH * SDIM];
__device__ __align__(256) float g_u  [BATCH * SDIM];
__device__ __align__(256) float g_res[BATCH * SDIM];
__device__ __align__(256) float g_WT [SDIM * SDIM];
__device__ __align__(256) float g_MA [SDIM * SDIM];
__device__ __align__(256) float g_MB [SDIM * SDIM];
__device__ __align__(256) uint4 g_FW [NTTILES * NCHUNK * 32];   // W  frags (hi,hi,lo,lo)
__device__ __align__(256) uint4 g_FWT[NTTILES * NCHUNK * 32];   // WT frags
__device__ __align__(256) float g_vec [SDIM];
__device__ __align__(256) float g_wvec[SDIM];
__device__ float g_scal[4];   // [0] = 1/L, [1] = thresh

// ---- eigen kernel smem (R8 layout) ----
#define AHI_OFF 0
#define ALO_OFF 2048
#define BHI_OFF 4096
#define BLO_OFF 8192
#define STAGE_B    12288
#define SMEM_TOTAL (2 * STAGE_B)   // 24 KB

// ---- FISTA kernel smem (A only) ----
#define STAGE_BF   4096            // Ahi[0,2K) Alo[2K,4K)
#define SMEM_BF    (2 * STAGE_BF)  // 8 KB

static __device__ __forceinline__ uint32_t smem_u32(const void* p) {
    uint32_t a;
    asm("{ .reg .u64 t; cvta.to.shared.u64 t, %1; cvt.u32.u64 %0, t; }" : "=r"(a) : "l"(p));
    return a;
}
static __device__ __forceinline__ uint32_t lds32(uint32_t a) {
    uint32_t v; asm volatile("ld.shared.b32 %0, [%1];" : "=r"(v) : "r"(a)); return v;
}
static __device__ __forceinline__ void sts64(uint32_t a, uint32_t v0, uint32_t v1) {
    asm volatile("st.shared.v2.b32 [%0], {%1,%2};" :: "r"(a), "r"(v0), "r"(v1));
}
static __device__ __forceinline__ void mma16816(float* d, const uint32_t* a, const uint32_t* b) {
    asm volatile(
        "mma.sync.aligned.m16n8k16.row.col.f32.bf16.bf16.f32 "
        "{%0,%1,%2,%3}, {%4,%5,%6,%7}, {%8,%9}, {%0,%1,%2,%3};"
        : "+f"(d[0]), "+f"(d[1]), "+f"(d[2]), "+f"(d[3])
        : "r"(a[0]), "r"(a[1]), "r"(a[2]), "r"(a[3]), "r"(b[0]), "r"(b[1]));
}
static __device__ __forceinline__ void mma16816v(float* d, const uint32_t* a,
                                                 uint32_t b0, uint32_t b1) {
    uint32_t b[2] = {b0, b1};
    mma16816(d, a, b);
}

// split float4 -> 2 packed bf16x2 hi (truncated) + 2 lo (rounded residual)
static __device__ __forceinline__ void split4(float4 v, uint32_t& h0, uint32_t& h1,
                                              uint32_t& l0, uint32_t& l1) {
    uint32_t u0 = __float_as_uint(v.x), u1 = __float_as_uint(v.y);
    uint32_t u2 = __float_as_uint(v.z), u3 = __float_as_uint(v.w);
    h0 = __byte_perm(u0, u1, 0x7632);
    h1 = __byte_perm(u2, u3, 0x7632);
    float a0 = v.x - __uint_as_float(u0 & 0xFFFF0000u);
    float a1 = v.y - __uint_as_float(u1 & 0xFFFF0000u);
    float a2 = v.z - __uint_as_float(u2 & 0xFFFF0000u);
    float a3 = v.w - __uint_as_float(u3 & 0xFFFF0000u);
    asm("cvt.rn.bf16x2.f32 %0, %1, %2;" : "=r"(l0) : "f"(a1), "f"(a0));
    asm("cvt.rn.bf16x2.f32 %0, %1, %2;" : "=r"(l1) : "f"(a3), "f"(a2));
}

static __device__ __forceinline__ float softthr(float v, float th) {
    float a = fabsf(v) - th;
    return a > 0.0f ? copysignf(a, v) : 0.0f;
}

// ---------------------------------------------------------------------------
// Eigen kernel (R8, unchanged): CTA 64x128, 4 warps 2x2, warp 32x64, SYM grid.
// ---------------------------------------------------------------------------
__global__ void __launch_bounds__(128, 3)
mma_gemm_sym(const float* __restrict__ A, const float* __restrict__ Bm,
             float* __restrict__ C, float scale)
{
    extern __shared__ char smem[];
    const uint32_t sb = smem_u32(smem);
    const int tid = threadIdx.x;
    const int wid = tid >> 5, lid = tid & 31;
    const int wm = wid & 1, wn = wid >> 1;

    int bid = blockIdx.x;
    int mac = bid >> 1, half0 = bid & 1;
    int by = (int)((sqrtf(8.0f * mac + 1.0f) - 1.0f) * 0.5f);
    while ((by + 1) * (by + 2) / 2 <= mac) by++;
    while (by * (by + 1) / 2 > mac) by--;
    int bx = mac - by * (by + 1) / 2;
    const int row0 = by * 128 + half0 * 64;
    const int col0 = bx * 128;
    const bool mirror = (bx != by);

    const int qa = tid & 3;
    const int rbase = tid >> 2;
    const int hp = qa >> 1;
    const int q1 = qa & 1;
    uint32_t aOff[2], bOff[4];
#pragma unroll
    for (int p = 0; p < 2; p++) {
        int r = rbase + 32 * p;
        int mt = r >> 4, rr = r & 15, rrq = rr & 7, r8 = rr >> 3;
        aOff[p] = (uint32_t)(((mt * 4 + hp * 2 + r8) * 32 + rrq * 4 + 2 * q1) * 4);
    }
#pragma unroll
    for (int p = 0; p < 4; p++) {
        int r = rbase + 32 * p;
        int nt = r >> 3, nn = r & 7;
        bOff[p] = (uint32_t)(((nt * 2 + hp) * 32 + nn * 4 + 2 * q1) * 4);
    }
    const float* Abase = A  + (size_t)(row0 + rbase) * SDIM + qa * 4;
    const float* Bbase = Bm + (size_t)(col0 + rbase) * SDIM + qa * 4;

    float acc[2][8][4];
#pragma unroll
    for (int i = 0; i < 2; i++)
#pragma unroll
        for (int j = 0; j < 8; j++)
#pragma unroll
            for (int q = 0; q < 4; q++) acc[i][j][q] = 0.0f;

    float4 pA[2], pB[4];

#define E_LDG(kt)                                                                  \
    do {                                                                           \
        _Pragma("unroll")                                                          \
        for (int p = 0; p < 2; p++)                                                \
            pA[p] = *reinterpret_cast<const float4*>(Abase + (size_t)(32 * p) * SDIM + (kt)); \
        _Pragma("unroll")                                                          \
        for (int p = 0; p < 4; p++)                                                \
            pB[p] = *reinterpret_cast<const float4*>(Bbase + (size_t)(32 * p) * SDIM + (kt)); \
    } while (0)

#define E_STS(stoff)                                                               \
    do {                                                                           \
        _Pragma("unroll")                                                          \
        for (int p = 0; p < 2; p++) {                                              \
            uint32_t h0, h1, l0, l1;                                               \
            split4(pA[p], h0, h1, l0, l1);                                         \
            sts64(sb + (stoff) + AHI_OFF + aOff[p], h0, h1);                       \
            sts64(sb + (stoff) + ALO_OFF + aOff[p], l0, l1);                       \
        }                                                                          \
        _Pragma("unroll")                                                          \
        for (int p = 0; p < 4; p++) {                                              \
            uint32_t h0, h1, l0, l1;                                               \
            split4(pB[p], h0, h1, l0, l1);                                         \
            sts64(sb + (stoff) + BHI_OFF + bOff[p], h0, h1);                       \
            sts64(sb + (stoff) + BLO_OFF + bOff[p], l0, l1);                       \
        }                                                                          \
    } while (0)

    E_LDG(0);
    E_STS(0u);
    __syncthreads();

    const uint32_t l4 = (uint32_t)(lid * 4);

#pragma unroll 1
    for (int c = 0; c < NCHUNK; c++) {
        if (c + 1 < NCHUNK) E_LDG((c + 1) * KCHUNK);

        const uint32_t s0 = sb + (uint32_t)((c & 1) * STAGE_B);
        uint32_t ah[2][4], al[2][4];
#pragma unroll
        for (int bm = 0; bm < 2; bm++) {
            int mt = wm * 2 + bm;
            uint32_t ab = s0 + (uint32_t)((mt * 4) * 128) + l4;
#pragma unroll
            for (int wi = 0; wi < 4; wi++) {
                ah[bm][wi] = lds32(ab + AHI_OFF + wi * 128);
                al[bm][wi] = lds32(ab + ALO_OFF + wi * 128);
            }
        }
#pragma unroll
        for (int half = 0; half < 2; half++) {
            uint32_t bh[4][2], bl[4][2];
#pragma unroll
            for (int j = 0; j < 4; j++) {
                int nt = wn * 8 + half * 4 + j;
                uint32_t bb = s0 + (uint32_t)((nt * 2) * 128) + l4;
                bh[j][0] = lds32(bb + BHI_OFF);
                bh[j][1] = lds32(bb + BHI_OFF + 128);
                bl[j][0] = lds32(bb + BLO_OFF);
                bl[j][1] = lds32(bb + BLO_OFF + 128);
            }
#pragma unroll
            for (int bm = 0; bm < 2; bm++)
#pragma unroll
                for (int j = 0; j < 4; j++)
                    mma16816(acc[bm][half * 4 + j], ah[bm], bh[j]);
#pragma unroll
            for (int bm = 0; bm < 2; bm++)
#pragma unroll
                for (int j = 0; j < 4; j++)
                    mma16816(acc[bm][half * 4 + j], ah[bm], bl[j]);
#pragma unroll
            for (int bm = 0; bm < 2; bm++)
#pragma unroll
                for (int j = 0; j < 4; j++)
                    mma16816(acc[bm][half * 4 + j], al[bm], bh[j]);
        }

        if (c + 1 < NCHUNK) E_STS((uint32_t)(((c + 1) & 1) * STAGE_B));
        __syncthreads();
    }

    const int gid = lid >> 2, tig = lid & 3;
#pragma unroll
    for (int bm = 0; bm < 2; bm++) {
#pragma unroll
        for (int bn = 0; bn < 8; bn++) {
            const int n = col0 + wn * 64 + bn * 8 + tig * 2;
#pragma unroll
            for (int hr = 0; hr < 2; hr++) {
                const int m = row0 + wm * 32 + bm * 16 + gid + hr * 8;
                float ax = acc[bm][bn][hr * 2 + 0] * scale;
                float ay = acc[bm][bn][hr * 2 + 1] * scale;
                const size_t idx = (size_t)m * SDIM + n;
                float2 o; o.x = ax; o.y = ay;
                *reinterpret_cast<float2*>(C + idx) = o;
                if (mirror) {
                    C[(size_t)n * SDIM + m]       = ax;
                    C[(size_t)(n + 1) * SDIM + m] = ay;
                }
            }
        }
    }
}

// ---------------------------------------------------------------------------
// build fragment-ready bf16 hi/lo split of a static B matrix.
// Layout: F[(nt*NCHUNK + c)*32 + lane] = {hi_k0pair, hi_k8pair, lo_k0pair, lo_k8pair}
// lane l -> n = nt*8 + (l>>2), kpair = l&3 (cols c*16 + kpair*2 + {0,1} and +8)
// ---------------------------------------------------------------------------
__global__ void build_bfrag(const float* __restrict__ B, uint4* __restrict__ F) {
    int nt = blockIdx.x, c = blockIdx.y, l = threadIdx.x;
    int n = nt * 8 + (l >> 2);
    int k0 = c * KCHUNK + (l & 3) * 2;
    const float* row = B + (size_t)n * SDIM;
    float a0 = row[k0], a1 = row[k0 + 1], b0 = row[k0 + 8], b1 = row[k0 + 9];
    uint32_t ua0 = __float_as_uint(a0), ua1 = __float_as_uint(a1);
    uint32_t ub0 = __float_as_uint(b0), ub1 = __float_as_uint(b1);
    uint4 w;
    w.x = __byte_perm(ua0, ua1, 0x7632);
    w.y = __byte_perm(ub0, ub1, 0x7632);
    float r0 = a0 - __uint_as_float(ua0 & 0xFFFF0000u);
    float r1 = a1 - __uint_as_float(ua1 & 0xFFFF0000u);
    float r2 = b0 - __uint_as_float(ub0 & 0xFFFF0000u);
    float r3 = b1 - __uint_as_float(ub1 & 0xFFFF0000u);
    asm("cvt.rn.bf16x2.f32 %0, %1, %2;" : "=r"(w.z) : "f"(r1), "f"(r0));
    asm("cvt.rn.bf16x2.f32 %0, %1, %2;" : "=r"(w.w) : "f"(r3), "f"(r2));
    F[((size_t)nt * NCHUNK + c) * 32 + l] = w;
}

// ---------------------------------------------------------------------------
// FISTA GEMM: C[m,n] = sum_k A[m,k]*B[n,k] with B given as static frag array.
// CTA 64(M)x128(N), 4 warps 2x2, warp 32x64. A via smem; B frags via LDG,
// register double-buffered one chunk ahead.
// EPI 1: res/u epilogue    EPI 2: FISTA update (+out)
// ---------------------------------------------------------------------------
template<int EPI>
__global__ void __launch_bounds__(128, 2)
mma_gemm_bf(const float* __restrict__ A, const uint4* __restrict__ FB,
            const float* __restrict__ src, const float* __restrict__ Yg,
            float* __restrict__ resv, float* __restrict__ uv,
            float* __restrict__ xth, float* __restrict__ yth,
            float* __restrict__ xdl, float* __restrict__ ydl,
            float* __restrict__ outp, float mom)
{
    extern __shared__ char smem[];
    const uint32_t sb = smem_u32(smem);
    const int tid = threadIdx.x;
    const int wid = tid >> 5, lid = tid & 31;
    const int wm = wid & 1, wn = wid >> 1;
    const int row0 = blockIdx.y * 64, col0 = blockIdx.x * 128;

    // A producer mapping (coalesced LDG, conflict-free STS.64)
    const int qa = tid & 3;
    const int rbase = tid >> 2;
    const int hp = qa >> 1, q1 = qa & 1;
    uint32_t aOff[2];
#pragma unroll
    for (int p = 0; p < 2; p++) {
        int r = rbase + 32 * p;
        int mt = r >> 4, rr = r & 15, rrq = rr & 7, r8 = rr >> 3;
        aOff[p] = (uint32_t)(((mt * 4 + hp * 2 + r8) * 32 + rrq * 4 + 2 * q1) * 4);
    }
    const float* Abase = A + (size_t)(row0 + rbase) * SDIM + qa * 4;

    // B fragment base for this warp: n-tiles nt0..nt0+7
    const uint4* Fbase = FB + ((size_t)((col0 >> 3) + wn * 8) * NCHUNK) * 32 + lid;

    float acc[2][8][4];
#pragma unroll
    for (int i = 0; i < 2; i++)
#pragma unroll
        for (int j = 0; j < 8; j++)
#pragma unroll
            for (int q = 0; q < 4; q++) acc[i][j][q] = 0.0f;

    float4 pA[2];
    uint4 bE[8], bO[8];

#define F_LDGA(kt)                                                                 \
    do {                                                                           \
        _Pragma("unroll")                                                          \
        for (int p = 0; p < 2; p++)                                                \
            pA[p] = *reinterpret_cast<const float4*>(Abase + (size_t)(32 * p) * SDIM + (kt)); \
    } while (0)

#define F_STSA(stoff)                                                              \
    do {                                                                           \
        _Pragma("unroll")                                                          \
        for (int p = 0; p < 2; p++) {                                              \
            uint32_t h0, h1, l0, l1;                                               \
            split4(pA[p], h0, h1, l0, l1);                                         \
            sts64(sb + (stoff) + aOff[p], h0, h1);                                 \
            sts64(sb + (stoff) + 2048u + aOff[p], l0, l1);                         \
        }                                                                          \
    } while (0)

#define F_LDGB(dst, cc)                                                            \
    do {                                                                           \
        _Pragma("unroll")                                                          \
        for (int t = 0; t < 8; t++)                                                \
            dst[t] = Fbase[((size_t)t * NCHUNK + (cc)) * 32];                      \
    } while (0)

#define F_CONSUME(stoff, BFR)                                                      \
    do {                                                                           \
        uint32_t ah[2][4], al[2][4];                                               \
        _Pragma("unroll")                                                          \
        for (int bm = 0; bm < 2; bm++) {                                           \
            int mt = wm * 2 + bm;                                                  \
            uint32_t ab = sb + (stoff) + (uint32_t)((mt * 4) * 128) + l4;          \
            _Pragma("unroll")                                                      \
            for (int wi = 0; wi < 4; wi++) {                                       \
                ah[bm][wi] = lds32(ab + wi * 128);                                 \
                al[bm][wi] = lds32(ab + 2048u + wi * 128);                         \
            }                                                                      \
        }                                                                          \
        _Pragma("unroll")                                                          \
        for (int bm = 0; bm < 2; bm++)                                             \
            _Pragma("unroll")                                                      \
            for (int t = 0; t < 8; t++)                                            \
                mma16816v(acc[bm][t], ah[bm], BFR[t].x, BFR[t].y);                 \
        _Pragma("unroll")                                                          \
        for (int bm = 0; bm < 2; bm++)                                             \
            _Pragma("unroll")                                                      \
            for (int t = 0; t < 8; t++)                                            \
                mma16816v(acc[bm][t], ah[bm], BFR[t].z, BFR[t].w);                 \
        _Pragma("unroll")                                                          \
        for (int bm = 0; bm < 2; bm++)                                             \
            _Pragma("unroll")                                                      \
            for (int t = 0; t < 8; t++)                                            \
                mma16816v(acc[bm][t], al[bm], BFR[t].x, BFR[t].y);                 \
    } while (0)

    F_LDGA(0);
    F_LDGB(bE, 0);
    F_STSA(0u);
    __syncthreads();

    const uint32_t l4 = (uint32_t)(lid * 4);

#pragma unroll 1
    for (int c = 0; c < NCHUNK; c += 2) {
        if (c + 1 < NCHUNK) { F_LDGA((c + 1) * KCHUNK); F_LDGB(bO, c + 1); }
        F_CONSUME(0u, bE);
        if (c + 1 < NCHUNK) F_STSA(STAGE_BF);
        __syncthreads();

        if (c + 2 < NCHUNK) { F_LDGA((c + 2) * KCHUNK); F_LDGB(bE, c + 2); }
        F_CONSUME((uint32_t)STAGE_BF, bO);
        if (c + 2 < NCHUNK) F_STSA(0u);
        __syncthreads();
    }

    // ---- epilogue ----
    const float invL = (EPI == 2) ? g_scal[0] : 0.0f;
    const float th   = (EPI == 2) ? g_scal[1] : 0.0f;
    const int gid = lid >> 2, tig = lid & 3;
#pragma unroll
    for (int bm = 0; bm < 2; bm++) {
#pragma unroll
        for (int bn = 0; bn < 8; bn++) {
            const int n = col0 + wn * 64 + bn * 8 + tig * 2;
#pragma unroll
            for (int hr = 0; hr < 2; hr++) {
                const int m = row0 + wm * 32 + bm * 16 + gid + hr * 8;
                float ax = acc[bm][bn][hr * 2 + 0];
                float ay = acc[bm][bn][hr * 2 + 1];
                const size_t idx = (size_t)m * SDIM + n;
                if (EPI == 1) {
                    float2 s  = *reinterpret_cast<const float2*>(src + idx);
                    float2 yv = *reinterpret_cast<const float2*>(Yg + idx);
                    float2 yd = *reinterpret_cast<const float2*>(ydl + idx);
                    float2 rr2, uu;
                    rr2.x = yv.x - s.x * ax - yd.x;  uu.x = s.x * rr2.x;
                    rr2.y = yv.y - s.y * ay - yd.y;  uu.y = s.y * rr2.y;
                    *reinterpret_cast<float2*>(resv + idx) = rr2;
                    *reinterpret_cast<float2*>(uv + idx)   = uu;
                } else {
                    float2 yt = *reinterpret_cast<const float2*>(yth + idx);
                    float2 xt = *reinterpret_cast<const float2*>(xth + idx);
                    float2 xn, yn;
                    xn.x = softthr(yt.x + ax * invL, th);  yn.x = xn.x + mom * (xn.x - xt.x);
                    xn.y = softthr(yt.y + ay * invL, th);  yn.y = xn.y + mom * (xn.y - xt.y);
                    *reinterpret_cast<float2*>(xth + idx) = xn;
                    *reinterpret_cast<float2*>(yth + idx) = yn;
                    float2 rs = *reinterpret_cast<const float2*>(resv + idx);
                    float2 yd = *reinterpret_cast<const float2*>(ydl + idx);
                    float2 xd = *reinterpret_cast<const float2*>(xdl + idx);
                    float2 xnd, ynd;
                    xnd.x = softthr(yd.x + rs.x * invL, th);  ynd.x = xnd.x + mom * (xnd.x - xd.x);
                    xnd.y = softthr(yd.y + rs.y * invL, th);  ynd.y = xnd.y + mom * (xnd.y - xd.y);
                    *reinterpret_cast<float2*>(xdl + idx) = xnd;
                    *reinterpret_cast<float2*>(ydl + idx) = ynd;
                    if (outp) {
                        const size_t ob = (size_t)m * (2 * SDIM) + n;
                        *reinterpret_cast<float2*>(outp + ob)        = xn;
                        *reinterpret_cast<float2*>(outp + ob + SDIM) = xnd;
                    }
                }
            }
        }
    }
}

// ---------------- helper kernels ----------------
__global__ void transpose_kernel(const float* __restrict__ in, float* __restrict__ out) {
    __shared__ float t[32][33];
    int bx = blockIdx.x * 32, by = blockIdx.y * 32;
    int x = bx + threadIdx.x;
#pragma unroll
    for (int i = threadIdx.y; i < 32; i += 8)
        t[i][threadIdx.x] = in[(size_t)(by + i) * SDIM + x];
    __syncthreads();
    int x2 = by + threadIdx.x;
#pragma unroll
    for (int i = threadIdx.y; i < 32; i += 8)
        out[(size_t)(bx + i) * SDIM + x2] = t[threadIdx.x][i];
}

// iteration-0 GEMM1 shortcut: y=0 -> res = Y, u = src*Y
__global__ void init_iter0_kernel(const float* __restrict__ src, const float* __restrict__ Yg,
                                  float* __restrict__ resv, float* __restrict__ uv) {
    int i = blockIdx.x * blockDim.x + threadIdx.x;
    float4 y = reinterpret_cast<const float4*>(Yg)[i];
    float4 s = reinterpret_cast<const float4*>(src)[i];
    reinterpret_cast<float4*>(resv)[i] = y;
    float4 u; u.x = s.x * y.x; u.y = s.y * y.y; u.z = s.z * y.z; u.w = s.w * y.w;
    reinterpret_cast<float4*>(uv)[i] = u;
}

__global__ void fill_kernel() {
    int i = blockIdx.x * blockDim.x + threadIdx.x;
    if (i < SDIM) {
        unsigned h = (unsigned)i * 2654435761u;
        h ^= h >> 13; h *= 2246822519u; h ^= h >> 16;
        g_vec[i] = (float)(h & 0xFFFF) / 65536.0f - 0.5f;
    }
}

__global__ void matvec_kernel(const float* __restrict__ H,
                              const float* __restrict__ x,
                              float* __restrict__ y) {
    int row = blockIdx.x;
    const float* hr = H + (size_t)row * SDIM;
    float s = 0.0f;
    for (int j = threadIdx.x; j < SDIM; j += 256) s += hr[j] * x[j];
#pragma unroll
    for (int o = 16; o > 0; o >>= 1) s += __shfl_xor_sync(0xffffffffu, s, o);
    __shared__ float part[8];
    int w = threadIdx.x >> 5;
    if ((threadIdx.x & 31) == 0) part[w] = s;
    __syncthreads();
    if (threadIdx.x == 0) {
        float t = 0.0f;
#pragma unroll
        for (int k = 0; k < 8; k++) t += part[k];
        y[row] = t;
    }
}

__global__ void normalize_kernel(const float* __restrict__ w, float* __restrict__ v) {
    float ss = 0.0f;
    for (int i = threadIdx.x; i < SDIM; i += 256) { float t = w[i]; ss += t * t; }
#pragma unroll
    for (int o = 16; o > 0; o >>= 1) ss += __shfl_xor_sync(0xffffffffu, ss, o);
    __shared__ float part[8];
    __shared__ float s_inv;
    int wd = threadIdx.x >> 5;
    if ((threadIdx.x & 31) == 0) part[wd] = ss;
    __syncthreads();
    if (threadIdx.x == 0) {
        float t = 0.0f;
        for (int i = 0; i < 8; i++) t += part[i];
        s_inv = rsqrtf(t);
    }
    __syncthreads();
    float inv = s_inv;
    for (int i = threadIdx.x; i < SDIM; i += 256) v[i] = w[i] * inv;
}

// Rayleigh on G'^64 (G' = G/4): L = 4 * lam^(1/64); writes 1/L and thresh.
__global__ void finalize_kernel(const float* __restrict__ v,
                                const float* __restrict__ w,
                                const float* __restrict__ alpha) {
    float num = 0.0f, den = 0.0f;
    for (int i = threadIdx.x; i < SDIM; i += 256) { num += v[i] * w[i]; den += v[i] * v[i]; }
#pragma unroll
    for (int o = 16; o > 0; o >>= 1) {
        num += __shfl_xor_sync(0xffffffffu, num, o);
        den += __shfl_xor_sync(0xffffffffu, den, o);
    }
    __shared__ float pn[8], pd[8];
    int wd = threadIdx.x >> 5;
    if ((threadIdx.x & 31) == 0) { pn[wd] = num; pd[wd] = den; }
    __syncthreads();
    if (threadIdx.x == 0) {
        double n = 0.0, d = 0.0;
        for (int i = 0; i < 8; i++) { n += pn[i]; d += pd[i]; }
        double lam = n / d;
        double L = 4.0 * pow(lam, 1.0 / 64.0);
        g_scal[0] = (float)(1.0 / L);
        g_scal[1] = (float)((double)alpha[0] * 0.5 / L);
    }
}

#define NSYMT (136 * 2)

extern "C" void kernel_launch(void* const* d_in, const int* in_sizes, int n_in,
                              void* d_out, int out_size) {
    (void)in_sizes; (void)n_in; (void)out_size;
    const float* src   = (const float*)d_in[0];
    const float* Y     = (const float*)d_in[1];
    const float* W     = (const float*)d_in[2];
    const float* alpha = (const float*)d_in[3];
    float* out = (float*)d_out;

    float *yth, *ydl, *xth, *xdl, *u, *res, *WT, *MA, *MB, *vec, *wvec;
    uint4 *FW, *FWT;
    cudaGetSymbolAddress((void**)&yth,  g_yth);
    cudaGetSymbolAddress((void**)&ydl,  g_ydl);
    cudaGetSymbolAddress((void**)&xth,  g_xth);
    cudaGetSymbolAddress((void**)&xdl,  g_xdl);
    cudaGetSymbolAddress((void**)&u,    g_u);
    cudaGetSymbolAddress((void**)&res,  g_res);
    cudaGetSymbolAddress((void**)&WT,   g_WT);
    cudaGetSymbolAddress((void**)&MA,   g_MA);
    cudaGetSymbolAddress((void**)&MB,   g_MB);
    cudaGetSymbolAddress((void**)&FW,   g_FW);
    cudaGetSymbolAddress((void**)&FWT,  g_FWT);
    cudaGetSymbolAddress((void**)&vec,  g_vec);
    cudaGetSymbolAddress((void**)&wvec, g_wvec);

    cudaFuncSetAttribute(mma_gemm_sym, cudaFuncAttributeMaxDynamicSharedMemorySize, SMEM_TOTAL);

    // WT = W^T, then fragment-split W and WT
    transpose_kernel<<<dim3(64, 64), dim3(32, 8)>>>(W, WT);
    build_bfrag<<<dim3(NTTILES, NCHUNK), 32>>>(W, FW);
    build_bfrag<<<dim3(NTTILES, NCHUNK), 32>>>(WT, FWT);

    // eigen chain: G' = (W^T W)/4, then 6 squarings -> G'^64 in MA
    mma_gemm_sym<<<NSYMT, 128, SMEM_TOTAL>>>(WT, WT, MA, 0.25f);
    mma_gemm_sym<<<NSYMT, 128, SMEM_TOTAL>>>(MA, MA, MB, 1.0f);
    mma_gemm_sym<<<NSYMT, 128, SMEM_TOTAL>>>(MB, MB, MA, 1.0f);
    mma_gemm_sym<<<NSYMT, 128, SMEM_TOTAL>>>(MA, MA, MB, 1.0f);
    mma_gemm_sym<<<NSYMT, 128, SMEM_TOTAL>>>(MB, MB, MA, 1.0f);
    mma_gemm_sym<<<NSYMT, 128, SMEM_TOTAL>>>(MA, MA, MB, 1.0f);
    mma_gemm_sym<<<NSYMT, 128, SMEM_TOTAL>>>(MB, MB, MA, 1.0f);

    // power iteration + Rayleigh on G'^64
    fill_kernel<<<(SDIM + 255) / 256, 256>>>();
    for (int i = 0; i < 2; i++) {
        for (int jj = 0; jj < 7; jj++) {
            matvec_kernel<<<SDIM, 256>>>(MA, vec, wvec);
            float* tmp = vec; vec = wvec; wvec = tmp;
        }
        matvec_kernel<<<SDIM, 256>>>(MA, vec, wvec);
        normalize_kernel<<<1, 256>>>(wvec, vec);
    }
    matvec_kernel<<<SDIM, 256>>>(MA, vec, wvec);
    finalize_kernel<<<1, 256>>>(vec, wvec, alpha);

    // FISTA state init (x0 = y0 = 0)
    size_t bytes = (size_t)BATCH * SDIM * sizeof(float);
    cudaMemsetAsync(yth, 0, bytes);
    cudaMemsetAsync(ydl, 0, bytes);
    cudaMemsetAsync(xth, 0, bytes);
    cudaMemsetAsync(xdl, 0, bytes);

    dim3 ga(SDIM / 128, BATCH / 64);   // 16 x 16 = 256 CTAs

    float t = 1.0f;
    for (int it = 0; it < N_ITER; it++) {
        float tn  = (1.0f + sqrtf(1.0f + 4.0f * t * t)) * 0.5f;
        float mom = (t - 1.0f) / tn;
        t = tn;
        float* op = (it == N_ITER - 1) ? out : nullptr;

        if (it == 0) {
            init_iter0_kernel<<<(BATCH * SDIM / 4 + 255) / 256, 256>>>(src, Y, res, u);
        } else {
            // Z = yth * W^T ; res = Y - src*Z - ydl ; u = src*res
            mma_gemm_bf<1><<<ga, 128, SMEM_BF>>>(yth, FW,
                src, Y, res, u, nullptr, nullptr, nullptr, ydl, nullptr, 0.0f);
        }
        // g = W^T u ; theta/delta soft-threshold + momentum (+ out)
        mma_gemm_bf<2><<<ga, 128, SMEM_BF>>>(u, FWT,
            nullptr, nullptr, res, nullptr, xth, yth, xdl, ydl, op, mom);
    }
}